// round 1
// baseline (speedup 1.0000x reference)
#include <cuda_runtime.h>
#include <math.h>

#define BB 64
#define NNODES 512
#define BN 32768
#define EE 524288
#define DA 70
#define DE 14
#define DH 200
#define DI 6
#define DC 16
#define TSCALE 0.07071067811865475f

// ---------------- device scratch (static; no allocations) ----------------
__device__ float g_h[2][BN * DH];    // node states (hln, then hln+agg)
__device__ float g_c[2][BN * DH];    // attention outputs
__device__ float g_hf[2][BN * DH];   // after W_down + degree table
__device__ int   g_deg[2][BN];
__device__ int   g_cnt[2][BN];
__device__ int   g_rowptr[2][BN + 1];
__device__ int   g_cursor[2][BN];
__device__ int   g_eidx[2][EE];
__device__ float g_x[BB * 618];

// ---------------- CSR build ----------------
__global__ void k_zero() {
    int i = blockIdx.x * blockDim.x + threadIdx.x;
    if (i < BN) { g_cnt[0][i] = 0; g_cnt[1][i] = 0; }
}

__global__ void k_count(const int* __restrict__ dst, int side) {
    int e = blockIdx.x * blockDim.x + threadIdx.x;
    if (e < EE) atomicAdd(&g_cnt[side][dst[e]], 1);
}

__global__ void k_scan(int side) {   // single block, 1024 threads
    __shared__ int s[1024];
    int t = threadIdx.x;
    int base = t * 32;
    int loc[32];
    int sum = 0;
#pragma unroll
    for (int i = 0; i < 32; i++) { loc[i] = g_cnt[side][base + i]; sum += loc[i]; }
    s[t] = sum;
    __syncthreads();
    int val = sum;
    for (int off = 1; off < 1024; off <<= 1) {
        int add = (t >= off) ? s[t - off] : 0;
        __syncthreads();
        val += add; s[t] = val;
        __syncthreads();
    }
    int run = val - sum;   // exclusive prefix across threads
    for (int i = 0; i < 32; i++) {
        g_rowptr[side][base + i] = run;
        g_cursor[side][base + i] = run;
        run += loc[i];
    }
    if (t == 1023) g_rowptr[side][BN] = run;
}

__global__ void k_fill(const int* __restrict__ dst, int side) {
    int e = blockIdx.x * blockDim.x + threadIdx.x;
    if (e < EE) {
        int slot = atomicAdd(&g_cursor[side][dst[e]], 1);
        g_eidx[side][slot] = e;
    }
}

// ---------------- atom path: hln = LN(relu(atom @ W_atom)) ----------------
__device__ __forceinline__ void ln_write(float* acc, int node, int l,
                                         const float* lg, const float* lb,
                                         float* out) {
    float s = 0.f, s2 = 0.f;
#pragma unroll
    for (int i = 0; i < 7; i++) {
        int k = l + 32 * i;
        if (k < DH) { float v = fmaxf(acc[i], 0.f); acc[i] = v; s += v; s2 += v * v; }
    }
#pragma unroll
    for (int o = 16; o > 0; o >>= 1) {
        s += __shfl_xor_sync(0xffffffffu, s, o);
        s2 += __shfl_xor_sync(0xffffffffu, s2, o);
    }
    float m = s * (1.0f / DH);
    float var = s2 * (1.0f / DH) - m * m;
    float rs = rsqrtf(var + 1e-5f);
#pragma unroll
    for (int i = 0; i < 7; i++) {
        int k = l + 32 * i;
        if (k < DH) out[node * DH + k] = lg[i] * (acc[i] - m) * rs + lb[i];
    }
}

__global__ void __launch_bounds__(256) k_atom(const float* __restrict__ atom,
                                              const float* __restrict__ W,
                                              const float* __restrict__ lng,
                                              const float* __restrict__ lnb,
                                              int side) {
    extern __shared__ float sm[];
    float* sW = sm;             // DA*DH
    float* sA = sm + DA * DH;   // 8 warps * 2 rows * DA
    float* out = g_h[side];
    int t = threadIdx.x;
    for (int i = t; i < DA * DH; i += 256) sW[i] = W[i];
    int w = t / 32, l = t % 32;
    float lg[7], lb[7];
#pragma unroll
    for (int i = 0; i < 7; i++) {
        int k = l + 32 * i;
        lg[i] = (k < DH) ? lng[k] : 0.f;
        lb[i] = (k < DH) ? lnb[k] : 0.f;
    }
    __syncthreads();
    float* myA = sA + w * 2 * DA;
    for (int pair = 0; pair < 2; pair++) {
        int n0 = (blockIdx.x * 8 + w) * 4 + pair * 2;   // warp handles 4 nodes (2 pairs)
        for (int j = l; j < 2 * DA; j += 32) myA[j] = atom[n0 * DA + j];
        __syncwarp();
        float a0[7], a1[7];
#pragma unroll
        for (int i = 0; i < 7; i++) { a0[i] = 0.f; a1[i] = 0.f; }
        for (int j = 0; j < DA; j++) {
            float x0 = myA[j], x1 = myA[DA + j];
#pragma unroll
            for (int i = 0; i < 7; i++) {
                int k = l + 32 * i;
                if (k < DH) {
                    float wv = sW[j * DH + k];
                    a0[i] = fmaf(x0, wv, a0[i]);
                    a1[i] = fmaf(x1, wv, a1[i]);
                }
            }
        }
        ln_write(a0, n0,     l, lg, lb, out);
        ln_write(a1, n0 + 1, l, lg, lb, out);
        __syncwarp();
    }
}

// ---------------- edge message gather: h += sum_edges LN([e||r]) ----------------
__global__ void __launch_bounds__(128) k_gather(const float* __restrict__ ef,
                                                const float* __restrict__ coords,
                                                const int* __restrict__ esrc,
                                                const float* __restrict__ W_edge,
                                                const float* __restrict__ W_rbf,
                                                const float* __restrict__ b_rbf,
                                                const float* __restrict__ lng,
                                                const float* __restrict__ lnb,
                                                int side) {
    __shared__ float s_ef[4][16];
    __shared__ float s_rbf[4][16];
    float* h = g_h[side];
    int* deg = g_deg[side];
    int t = threadIdx.x, w = t / 32, l = t % 32;

    // per-lane register cache of W columns (k = l + 32*i)
    float Wr[7][16];
    float br[7], lg[7], lb[7];
    bool isE[7], valid[7];
#pragma unroll
    for (int i = 0; i < 7; i++) {
        int k = l + 32 * i;
        valid[i] = (k < DH);
        isE[i] = (k < 100);
        lg[i] = valid[i] ? lng[k] : 0.f;
        lb[i] = valid[i] ? lnb[k] : 0.f;
        br[i] = 0.f;
#pragma unroll
        for (int j = 0; j < 16; j++) Wr[i][j] = 0.f;
        if (valid[i]) {
            if (k < 100) {
                for (int j = 0; j < DE; j++) Wr[i][j] = W_edge[j * 100 + k];
            } else {
                int kk = k - 100;
                for (int j = 0; j < DC; j++) Wr[i][j] = W_rbf[j * 100 + kk];
                br[i] = b_rbf[kk];
            }
        }
    }

    int warp_global = blockIdx.x * 4 + w;
    int nwarps = gridDim.x * 4;
    for (int node = warp_global; node < BN; node += nwarps) {
        int r0 = g_rowptr[side][node], r1 = g_rowptr[side][node + 1];
        float acc[7];
#pragma unroll
        for (int i = 0; i < 7; i++)
            acc[i] = valid[i] ? h[node * DH + l + 32 * i] : 0.f;
        float cdx = coords[node * 3 + 0];
        float cdy = coords[node * 3 + 1];
        float cdz = coords[node * 3 + 2];
        for (int e = r0; e < r1; e++) {
            int eid = g_eidx[side][e];
            int src = esrc[eid];
            if (l < DE) s_ef[w][l] = ef[eid * DE + l];
            float dx = coords[src * 3 + 0] - cdx;
            float dy = coords[src * 3 + 1] - cdy;
            float dz = coords[src * 3 + 2] - cdz;
            float dist = sqrtf(dx * dx + dy * dy + dz * dz + 1e-12f);
            if (l < DC) {
                float u = (dist - (float)l * (5.0f / 15.0f)) * (1.0f / 0.3125f);
                s_rbf[w][l] = __expf(-u * u);
            }
            __syncwarp();
            float v[7];
            float s = 0.f, s2 = 0.f;
#pragma unroll
            for (int i = 0; i < 7; i++) {
                float a = br[i];
                if (isE[i]) {
#pragma unroll
                    for (int j = 0; j < DE; j++) a = fmaf(s_ef[w][j], Wr[i][j], a);
                } else {
#pragma unroll
                    for (int j = 0; j < DC; j++) a = fmaf(s_rbf[w][j], Wr[i][j], a);
                }
                a = fmaxf(a, 0.f);
                if (!valid[i]) a = 0.f;
                v[i] = a; s += a; s2 += a * a;
            }
#pragma unroll
            for (int o = 16; o > 0; o >>= 1) {
                s += __shfl_xor_sync(0xffffffffu, s, o);
                s2 += __shfl_xor_sync(0xffffffffu, s2, o);
            }
            float mean = s * (1.0f / DH);
            float var = s2 * (1.0f / DH) - mean * mean;
            float rs = rsqrtf(var + 1e-5f);
#pragma unroll
            for (int i = 0; i < 7; i++)
                if (valid[i]) acc[i] += lg[i] * (v[i] - mean) * rs + lb[i];
            __syncwarp();
        }
        int d = r1 - r0;
        deg[node] = d > 199 ? 199 : d;
#pragma unroll
        for (int i = 0; i < 7; i++)
            if (valid[i]) h[node * DH + l + 32 * i] = acc[i];
    }
}

// ---------------- flash cross-attention (fp32 SIMT) ----------------
// side=0: out c1 = softmax_row(h1 h2^T * s) @ h2 ; side=1: c2 = attn(Q=h2, KV=h1)
#define ATM 64
#define ATK 64
#define QSTR 201
#define SSTR 65

__global__ void __launch_bounds__(256) k_attn(int side) {
    extern __shared__ float sm[];
    float* sQ = sm;                       // ATM*QSTR
    float* sK = sQ + ATM * QSTR;          // ATK*QSTR
    float* sS = sK + ATK * QSTR;          // ATM*SSTR
    float* sM = sS + ATM * SSTR;          // ATM
    float* sL = sM + ATM;                 // ATM
    float* sC = sL + ATM;                 // ATM

    const float* Q  = g_h[side];
    const float* KV = g_h[side ^ 1];
    float* O        = g_c[side];

    int t = threadIdx.x;
    int b = blockIdx.y;
    int q0 = blockIdx.x * ATM;
    const float* Qb = Q + (b * NNODES + q0) * DH;
    const float* Kb = KV + b * NNODES * DH;

    for (int i = t; i < ATM * DH; i += 256) {
        int r = i / DH, d = i % DH;
        sQ[r * QSTR + d] = Qb[r * DH + d];
    }
    if (t < ATM) { sM[t] = -1e30f; sL[t] = 0.f; }

    int w = t / 32, l = t % 32;
    int ty = t / 16, tx = t % 16;
    float Ov[8][7];
#pragma unroll
    for (int r = 0; r < 8; r++)
#pragma unroll
        for (int i = 0; i < 7; i++) Ov[r][i] = 0.f;
    __syncthreads();

    for (int kt = 0; kt < NNODES / ATK; kt++) {
        for (int i = t; i < ATK * DH; i += 256) {
            int r = i / DH, d = i % DH;
            sK[r * QSTR + d] = Kb[(kt * ATK + r) * DH + d];
        }
        __syncthreads();

        // S tile: thread (ty,tx) owns rows ty+16j, cols tx+16i
        float sa[4][4];
#pragma unroll
        for (int j = 0; j < 4; j++)
#pragma unroll
            for (int i = 0; i < 4; i++) sa[j][i] = 0.f;
        for (int d = 0; d < DH; d++) {
            float qv[4], kv[4];
#pragma unroll
            for (int j = 0; j < 4; j++) qv[j] = sQ[(ty + 16 * j) * QSTR + d];
#pragma unroll
            for (int i = 0; i < 4; i++) kv[i] = sK[(tx + 16 * i) * QSTR + d];
#pragma unroll
            for (int j = 0; j < 4; j++)
#pragma unroll
                for (int i = 0; i < 4; i++) sa[j][i] = fmaf(qv[j], kv[i], sa[j][i]);
        }
#pragma unroll
        for (int j = 0; j < 4; j++)
#pragma unroll
            for (int i = 0; i < 4; i++)
                sS[(ty + 16 * j) * SSTR + tx + 16 * i] = sa[j][i] * TSCALE;
        __syncthreads();

        // online softmax: 4 threads per row
        {
            int r = t / 4, part = t % 4;
            float mx = -1e30f;
            for (int c = part * 16; c < part * 16 + 16; c++)
                mx = fmaxf(mx, sS[r * SSTR + c]);
            mx = fmaxf(mx, __shfl_xor_sync(0xffffffffu, mx, 1));
            mx = fmaxf(mx, __shfl_xor_sync(0xffffffffu, mx, 2));
            float m_old = sM[r];
            float m_new = fmaxf(m_old, mx);
            float lsum = 0.f;
            for (int c = part * 16; c < part * 16 + 16; c++) {
                float p = __expf(sS[r * SSTR + c] - m_new);
                sS[r * SSTR + c] = p;
                lsum += p;
            }
            lsum += __shfl_xor_sync(0xffffffffu, lsum, 1);
            lsum += __shfl_xor_sync(0xffffffffu, lsum, 2);
            if (part == 0) {
                float corr = __expf(m_old - m_new);
                sC[r] = corr;
                sL[r] = sL[r] * corr + lsum;
                sM[r] = m_new;
            }
        }
        __syncthreads();

        // rescale + PV: warp w owns rows w*8..w*8+7, lane covers d = l + 32*i
#pragma unroll
        for (int r = 0; r < 8; r++) {
            float corr = sC[w * 8 + r];
#pragma unroll
            for (int i = 0; i < 7; i++) Ov[r][i] *= corr;
        }
        for (int c = 0; c < ATK; c++) {
            float vv[7];
#pragma unroll
            for (int i = 0; i < 7; i++) {
                int d = l + 32 * i;
                vv[i] = (d < DH) ? sK[c * QSTR + d] : 0.f;
            }
#pragma unroll
            for (int r = 0; r < 8; r++) {
                float p = sS[(w * 8 + r) * SSTR + c];
#pragma unroll
                for (int i = 0; i < 7; i++) Ov[r][i] = fmaf(p, vv[i], Ov[r][i]);
            }
        }
        __syncthreads();
    }

    float* Ob = O + (b * NNODES + q0) * DH;
#pragma unroll
    for (int r = 0; r < 8; r++) {
        float inv = 1.0f / sL[w * 8 + r];
#pragma unroll
        for (int i = 0; i < 7; i++) {
            int d = l + 32 * i;
            if (d < DH) Ob[(w * 8 + r) * DH + d] = Ov[r][i] * inv;
        }
    }
}

// ---------------- down projection: relu([h||c] @ W_down) + degree_table ----------------
__global__ void __launch_bounds__(256) k_down(const float* __restrict__ Wd,
                                              const float* __restrict__ dtab,
                                              int side) {
    extern __shared__ float sm[];
    float* sA = sm;              // 64*51
    float* sB = sm + 64 * 51;    // 50*201
    const float* h = g_h[side];
    const float* c = g_c[side];
    const int* deg = g_deg[side];
    float* out = g_hf[side];

    int t = threadIdx.x, w = t / 32, l = t % 32;
    int n0 = blockIdx.x * 64;
    float acc[8][7];
#pragma unroll
    for (int r = 0; r < 8; r++)
#pragma unroll
        for (int i = 0; i < 7; i++) acc[r][i] = 0.f;

    for (int ch = 0; ch < 8; ch++) {
        int k0 = ch * 50;
        for (int i = t; i < 64 * 50; i += 256) {
            int r = i / 50, kk = i % 50;
            int j = k0 + kk;
            float vv = (j < DH) ? h[(n0 + r) * DH + j] : c[(n0 + r) * DH + j - DH];
            sA[r * 51 + kk] = vv;
        }
        for (int i = t; i < 50 * DH; i += 256) {
            int kk = i / DH, d = i % DH;
            sB[kk * QSTR + d] = Wd[(k0 + kk) * DH + d];
        }
        __syncthreads();
        for (int kk = 0; kk < 50; kk++) {
            float bv[7];
#pragma unroll
            for (int i = 0; i < 7; i++) {
                int d = l + 32 * i;
                bv[i] = (d < DH) ? sB[kk * QSTR + d] : 0.f;
            }
#pragma unroll
            for (int r = 0; r < 8; r++) {
                float a = sA[(w * 8 + r) * 51 + kk];
#pragma unroll
                for (int i = 0; i < 7; i++) acc[r][i] = fmaf(a, bv[i], acc[r][i]);
            }
        }
        __syncthreads();
    }
#pragma unroll
    for (int r = 0; r < 8; r++) {
        int node = n0 + w * 8 + r;
        int dg = deg[node];
#pragma unroll
        for (int i = 0; i < 7; i++) {
            int d = l + 32 * i;
            if (d < DH)
                out[node * DH + d] = fmaxf(acc[r][i], 0.f) + dtab[dg * DH + d];
        }
    }
}

// ---------------- readout means -> x[64][618] ----------------
__global__ void k_means(const float* __restrict__ i1, const float* __restrict__ i2) {
    int b = blockIdx.x, t = threadIdx.x;
    if (t < DH) {
        float s1 = 0.f, s2 = 0.f;
        for (int n = 0; n < NNODES; n++) {
            s1 += g_hf[0][(b * NNODES + n) * DH + t];
            s2 += g_hf[1][(b * NNODES + n) * DH + t];
        }
        s1 *= (1.0f / NNODES); s2 *= (1.0f / NNODES);
        g_x[b * 618 + t] = s1;
        g_x[b * 618 + 206 + t] = s2;
        g_x[b * 618 + 412 + t] = s1 - s2;
    } else if (t < DH + DI) {
        int j = t - DH;
        float s1 = 0.f, s2 = 0.f;
        for (int n = 0; n < NNODES; n++) {
            s1 += i1[(b * NNODES + n) * DI + j];
            s2 += i2[(b * NNODES + n) * DI + j];
        }
        s1 *= (1.0f / NNODES); s2 *= (1.0f / NNODES);
        g_x[b * 618 + 200 + j] = s1;
        g_x[b * 618 + 406 + j] = s2;
        g_x[b * 618 + 612 + j] = s1 - s2;
    }
}

// ---------------- readout MLP ----------------
__global__ void k_mlp(const float* __restrict__ W1, const float* __restrict__ b1,
                      const float* __restrict__ W2, const float* __restrict__ b2,
                      const float* __restrict__ W3, const float* __restrict__ b3,
                      const float* __restrict__ W4, const float* __restrict__ b4,
                      float* __restrict__ out) {
    __shared__ float sx[618], s1[400], s2[200], s3[100];
    int b = blockIdx.x, t = threadIdx.x;
    for (int i = t; i < 618; i += 256) sx[i] = g_x[b * 618 + i];
    __syncthreads();
    for (int o = t; o < 400; o += 256) {
        float a = b1[o];
        for (int j = 0; j < 618; j++) a = fmaf(sx[j], W1[j * 400 + o], a);
        s1[o] = fmaxf(a, 0.f);
    }
    __syncthreads();
    for (int o = t; o < 200; o += 256) {
        float a = b2[o];
        for (int j = 0; j < 400; j++) a = fmaf(s1[j], W2[j * 200 + o], a);
        s2[o] = fmaxf(a, 0.f);
    }
    __syncthreads();
    for (int o = t; o < 100; o += 256) {
        float a = b3[o];
        for (int j = 0; j < 200; j++) a = fmaf(s2[j], W3[j * 100 + o], a);
        s3[o] = fmaxf(a, 0.f);
    }
    __syncthreads();
    if (t < 32) {
        float a = 0.f;
        for (int j = t; j < 100; j += 32) a = fmaf(s3[j], W4[j], a);
#pragma unroll
        for (int o = 16; o > 0; o >>= 1) a += __shfl_xor_sync(0xffffffffu, a, o);
        if (t == 0) out[b] = a + b4[0];
    }
}

// ---------------- launch ----------------
extern "C" void kernel_launch(void* const* d_in, const int* in_sizes, int n_in,
                              void* d_out, int out_size) {
    const float* atom1  = (const float*)d_in[0];
    const float* atom2  = (const float*)d_in[1];
    const float* coords1 = (const float*)d_in[2];
    const float* coords2 = (const float*)d_in[3];
    const float* ef1    = (const float*)d_in[4];
    const float* ef2    = (const float*)d_in[5];
    const float* int1   = (const float*)d_in[6];
    const float* int2   = (const float*)d_in[7];
    const int*   src1   = (const int*)d_in[8];
    const int*   dst1   = (const int*)d_in[9];
    const int*   src2   = (const int*)d_in[10];
    const int*   dst2   = (const int*)d_in[11];
    const float* W_atom = (const float*)d_in[12];
    const float* W_edge = (const float*)d_in[13];
    const float* W_rbf  = (const float*)d_in[14];
    const float* b_rbf  = (const float*)d_in[15];
    const float* ln_g   = (const float*)d_in[16];
    const float* ln_b   = (const float*)d_in[17];
    const float* W_down = (const float*)d_in[18];
    const float* dtab   = (const float*)d_in[19];
    const float* W_f1   = (const float*)d_in[20];
    const float* b_f1   = (const float*)d_in[21];
    const float* W_f2   = (const float*)d_in[22];
    const float* b_f2   = (const float*)d_in[23];
    const float* W_f3   = (const float*)d_in[24];
    const float* b_f3   = (const float*)d_in[25];
    const float* W_f4   = (const float*)d_in[26];
    const float* b_f4   = (const float*)d_in[27];
    float* out = (float*)d_out;

    const int SMEM_ATOM = (DA * DH + 8 * 2 * DA) * 4;                      // 60480
    const int SMEM_ATTN = (ATM * QSTR + ATK * QSTR + ATM * SSTR + 3 * ATM) * 4; // 120320
    const int SMEM_DOWN = (64 * 51 + 50 * QSTR) * 4;                       // 53256

    cudaFuncSetAttribute(k_atom, cudaFuncAttributeMaxDynamicSharedMemorySize, SMEM_ATOM);
    cudaFuncSetAttribute(k_attn, cudaFuncAttributeMaxDynamicSharedMemorySize, SMEM_ATTN);
    cudaFuncSetAttribute(k_down, cudaFuncAttributeMaxDynamicSharedMemorySize, SMEM_DOWN);

    // CSR build (both sides)
    k_zero<<<BN / 256, 256>>>();
    k_count<<<EE / 256, 256>>>(dst1, 0);
    k_count<<<EE / 256, 256>>>(dst2, 1);
    k_scan<<<1, 1024>>>(0);
    k_scan<<<1, 1024>>>(1);
    k_fill<<<EE / 256, 256>>>(dst1, 0);
    k_fill<<<EE / 256, 256>>>(dst2, 1);

    // atom GEMM + layernorm
    k_atom<<<BN / 32, 256, SMEM_ATOM>>>(atom1, W_atom, ln_g, ln_b, 0);
    k_atom<<<BN / 32, 256, SMEM_ATOM>>>(atom2, W_atom, ln_g, ln_b, 1);

    // edge message gather (recompute at consumer; no float atomics)
    k_gather<<<512, 128>>>(ef1, coords1, src1, W_edge, W_rbf, b_rbf, ln_g, ln_b, 0);
    k_gather<<<512, 128>>>(ef2, coords2, src2, W_edge, W_rbf, b_rbf, ln_g, ln_b, 1);

    // bidirectional cross attention
    dim3 agrid(NNODES / ATM, BB);
    k_attn<<<agrid, 256, SMEM_ATTN>>>(0);
    k_attn<<<agrid, 256, SMEM_ATTN>>>(1);

    // down projection + degree embedding
    k_down<<<BN / 64, 256, SMEM_DOWN>>>(W_down, dtab, 0);
    k_down<<<BN / 64, 256, SMEM_DOWN>>>(W_down, dtab, 1);

    // readout
    k_means<<<BB, 256>>>(int1, int2);
    k_mlp<<<BB, 256>>>(W_f1, b_f1, W_f2, b_f2, W_f3, b_f3, W_f4, b_f4, out);
}

// round 2
// speedup vs baseline: 1.3705x; 1.3705x over previous
#include <cuda_runtime.h>
#include <math.h>

#define BB 64
#define NNODES 512
#define BN 32768
#define EE 524288
#define DA 70
#define DE 14
#define DH 200
#define DI 6
#define DC 16
#define TSCALE 0.07071067811865475f

typedef unsigned long long ull;

// ---------------- f32x2 packed-FMA helpers (sm_100+ PTX 8.6) ----------------
__device__ __forceinline__ ull fma2(ull a, ull b, ull c) {
    ull d;
    asm("fma.rn.f32x2 %0, %1, %2, %3;" : "=l"(d) : "l"(a), "l"(b), "l"(c));
    return d;
}
__device__ __forceinline__ ull mul2(ull a, ull b) {
    ull d;
    asm("mul.rn.f32x2 %0, %1, %2;" : "=l"(d) : "l"(a), "l"(b));
    return d;
}
__device__ __forceinline__ ull pack2(float x, float y) {
    ull r;
    asm("mov.b64 %0, {%1, %2};" : "=l"(r) : "f"(x), "f"(y));
    return r;
}
__device__ __forceinline__ float2 unp2(ull a) {
    float2 f;
    asm("mov.b64 {%0, %1}, %2;" : "=f"(f.x), "=f"(f.y) : "l"(a));
    return f;
}
__device__ __forceinline__ ull ld2s(const float* p) {
    return *reinterpret_cast<const ull*>(p);
}

// ---------------- device scratch (static; no allocations) ----------------
__device__ float g_h[2][BN * DH];    // node states (hln, then hln+agg)
__device__ float g_c[2][BN * DH];    // attention outputs
__device__ float g_hf[2][BN * DH];   // after W_down + degree table
__device__ int   g_deg[2][BN];
__device__ int   g_cnt[2][BN];
__device__ int   g_rowptr[2][BN + 1];
__device__ int   g_cursor[2][BN];
__device__ int   g_eidx[2][EE];

// ---------------- atom path: hln = LN(relu(atom @ W_atom)); also zero counters ----------------
__device__ __forceinline__ void ln_write(float* acc, int node, int l,
                                         const float* lg, const float* lb,
                                         float* out) {
    float s = 0.f, s2 = 0.f;
#pragma unroll
    for (int i = 0; i < 7; i++) {
        int k = l + 32 * i;
        if (k < DH) { float v = fmaxf(acc[i], 0.f); acc[i] = v; s += v; s2 += v * v; }
    }
#pragma unroll
    for (int o = 16; o > 0; o >>= 1) {
        s += __shfl_xor_sync(0xffffffffu, s, o);
        s2 += __shfl_xor_sync(0xffffffffu, s2, o);
    }
    float m = s * (1.0f / DH);
    float var = s2 * (1.0f / DH) - m * m;
    float rs = rsqrtf(var + 1e-5f);
#pragma unroll
    for (int i = 0; i < 7; i++) {
        int k = l + 32 * i;
        if (k < DH) out[node * DH + k] = lg[i] * (acc[i] - m) * rs + lb[i];
    }
}

__global__ void __launch_bounds__(256) k_atom(const float* __restrict__ a1,
                                              const float* __restrict__ a2,
                                              const float* __restrict__ W,
                                              const float* __restrict__ lng,
                                              const float* __restrict__ lnb) {
    extern __shared__ float sm[];
    float* sW = sm;             // DA*DH
    float* sA = sm + DA * DH;   // 8 warps * 2 rows * DA
    int side = blockIdx.y;
    const float* atom = side ? a2 : a1;
    float* out = g_h[side];
    int t = threadIdx.x;
    // fold counter zeroing in (runs before k_count)
    int gid = blockIdx.x * 256 + t;
    if (gid < BN) g_cnt[side][gid] = 0;

    for (int i = t; i < DA * DH; i += 256) sW[i] = W[i];
    int w = t / 32, l = t % 32;
    float lg[7], lb[7];
#pragma unroll
    for (int i = 0; i < 7; i++) {
        int k = l + 32 * i;
        lg[i] = (k < DH) ? lng[k] : 0.f;
        lb[i] = (k < DH) ? lnb[k] : 0.f;
    }
    __syncthreads();
    float* myA = sA + w * 2 * DA;
    for (int pair = 0; pair < 2; pair++) {
        int n0 = (blockIdx.x * 8 + w) * 4 + pair * 2;
        for (int j = l; j < 2 * DA; j += 32) myA[j] = atom[n0 * DA + j];
        __syncwarp();
        float a0[7], a1v[7];
#pragma unroll
        for (int i = 0; i < 7; i++) { a0[i] = 0.f; a1v[i] = 0.f; }
        for (int j = 0; j < DA; j++) {
            float x0 = myA[j], x1 = myA[DA + j];
#pragma unroll
            for (int i = 0; i < 7; i++) {
                int k = l + 32 * i;
                if (k < DH) {
                    float wv = sW[j * DH + k];
                    a0[i] = fmaf(x0, wv, a0[i]);
                    a1v[i] = fmaf(x1, wv, a1v[i]);
                }
            }
        }
        ln_write(a0, n0,     l, lg, lb, out);
        ln_write(a1v, n0 + 1, l, lg, lb, out);
        __syncwarp();
    }
}

// ---------------- CSR build ----------------
__global__ void k_count(const int* __restrict__ d1, const int* __restrict__ d2) {
    int side = blockIdx.y;
    const int* dst = side ? d2 : d1;
    int e = blockIdx.x * blockDim.x + threadIdx.x;
    if (e < EE) atomicAdd(&g_cnt[side][dst[e]], 1);
}

__global__ void k_scan() {   // grid=2 (one block per side), 1024 threads
    int side = blockIdx.x;
    __shared__ int ws[32];
    int t = threadIdx.x;
    int base = t * 32;
    int loc[32];
    int sum = 0;
#pragma unroll
    for (int i = 0; i < 32; i++) { loc[i] = g_cnt[side][base + i]; sum += loc[i]; }
    int l = t & 31, w = t >> 5;
    int v = sum;
#pragma unroll
    for (int off = 1; off < 32; off <<= 1) {
        int n = __shfl_up_sync(0xffffffffu, v, off);
        if (l >= off) v += n;
    }
    if (l == 31) ws[w] = v;
    __syncthreads();
    if (w == 0) {
        int x = ws[l];
#pragma unroll
        for (int off = 1; off < 32; off <<= 1) {
            int n = __shfl_up_sync(0xffffffffu, x, off);
            if (l >= off) x += n;
        }
        ws[l] = x;
    }
    __syncthreads();
    int excl = v - sum + (w > 0 ? ws[w - 1] : 0);
    int run = excl;
    for (int i = 0; i < 32; i++) {
        g_rowptr[side][base + i] = run;
        g_cursor[side][base + i] = run;
        run += loc[i];
    }
    if (t == 1023) g_rowptr[side][BN] = run;
}

__global__ void k_fill(const int* __restrict__ d1, const int* __restrict__ d2) {
    int side = blockIdx.y;
    const int* dst = side ? d2 : d1;
    int e = blockIdx.x * blockDim.x + threadIdx.x;
    if (e < EE) {
        int slot = atomicAdd(&g_cursor[side][dst[e]], 1);
        g_eidx[side][slot] = e;
    }
}

// ---------------- edge message gather: h += sum_edges LN([e||r]) ----------------
__global__ void __launch_bounds__(128) k_gather(const float* __restrict__ ef1,
                                                const float* __restrict__ ef2,
                                                const float* __restrict__ co1,
                                                const float* __restrict__ co2,
                                                const int* __restrict__ s1,
                                                const int* __restrict__ s2,
                                                const float* __restrict__ W_edge,
                                                const float* __restrict__ W_rbf,
                                                const float* __restrict__ b_rbf,
                                                const float* __restrict__ lng,
                                                const float* __restrict__ lnb) {
    __shared__ float s_ef[4][16];
    __shared__ float s_rbf[4][16];
    int side = blockIdx.y;
    const float* ef = side ? ef2 : ef1;
    const float* coords = side ? co2 : co1;
    const int* esrc = side ? s2 : s1;
    float* h = g_h[side];
    int* deg = g_deg[side];
    int t = threadIdx.x, w = t / 32, l = t % 32;

    float Wr[7][16];
    float br[7], lg[7], lb[7];
    bool isE[7], valid[7];
#pragma unroll
    for (int i = 0; i < 7; i++) {
        int k = l + 32 * i;
        valid[i] = (k < DH);
        isE[i] = (k < 100);
        lg[i] = valid[i] ? lng[k] : 0.f;
        lb[i] = valid[i] ? lnb[k] : 0.f;
        br[i] = 0.f;
#pragma unroll
        for (int j = 0; j < 16; j++) Wr[i][j] = 0.f;
        if (valid[i]) {
            if (k < 100) {
                for (int j = 0; j < DE; j++) Wr[i][j] = W_edge[j * 100 + k];
            } else {
                int kk = k - 100;
                for (int j = 0; j < DC; j++) Wr[i][j] = W_rbf[j * 100 + kk];
                br[i] = b_rbf[kk];
            }
        }
    }

    int warp_global = blockIdx.x * 4 + w;
    int nwarps = gridDim.x * 4;
    for (int node = warp_global; node < BN; node += nwarps) {
        int r0 = g_rowptr[side][node], r1 = g_rowptr[side][node + 1];
        float acc[7];
#pragma unroll
        for (int i = 0; i < 7; i++)
            acc[i] = valid[i] ? h[node * DH + l + 32 * i] : 0.f;
        float cdx = coords[node * 3 + 0];
        float cdy = coords[node * 3 + 1];
        float cdz = coords[node * 3 + 2];
        for (int e = r0; e < r1; e++) {
            int eid = g_eidx[side][e];
            int src = esrc[eid];
            if (l < DE) s_ef[w][l] = ef[eid * DE + l];
            float dx = coords[src * 3 + 0] - cdx;
            float dy = coords[src * 3 + 1] - cdy;
            float dz = coords[src * 3 + 2] - cdz;
            float dist = sqrtf(dx * dx + dy * dy + dz * dz + 1e-12f);
            if (l < DC) {
                float u = (dist - (float)l * (5.0f / 15.0f)) * (1.0f / 0.3125f);
                s_rbf[w][l] = __expf(-u * u);
            }
            __syncwarp();
            float v[7];
            float s = 0.f, s2v = 0.f;
#pragma unroll
            for (int i = 0; i < 7; i++) {
                float a = br[i];
                if (isE[i]) {
#pragma unroll
                    for (int j = 0; j < DE; j++) a = fmaf(s_ef[w][j], Wr[i][j], a);
                } else {
#pragma unroll
                    for (int j = 0; j < DC; j++) a = fmaf(s_rbf[w][j], Wr[i][j], a);
                }
                a = fmaxf(a, 0.f);
                if (!valid[i]) a = 0.f;
                v[i] = a; s += a; s2v += a * a;
            }
#pragma unroll
            for (int o = 16; o > 0; o >>= 1) {
                s += __shfl_xor_sync(0xffffffffu, s, o);
                s2v += __shfl_xor_sync(0xffffffffu, s2v, o);
            }
            float mean = s * (1.0f / DH);
            float var = s2v * (1.0f / DH) - mean * mean;
            float rs = rsqrtf(var + 1e-5f);
#pragma unroll
            for (int i = 0; i < 7; i++)
                if (valid[i]) acc[i] += lg[i] * (v[i] - mean) * rs + lb[i];
            __syncwarp();
        }
        int d = r1 - r0;
        deg[node] = d > 199 ? 199 : d;
#pragma unroll
        for (int i = 0; i < 7; i++)
            if (valid[i]) h[node * DH + l + 32 * i] = acc[i];
    }
}

// ---------------- flash cross-attention (fp32, f32x2 packed FMA) ----------------
#define ATM 64
#define ATK 64
#define QSTR 202
#define SSTR 65

__global__ void __launch_bounds__(256) k_attn() {
    extern __shared__ float sm[];
    float* sQ = sm;                       // ATM*QSTR
    float* sK = sQ + ATM * QSTR;          // ATK*QSTR
    float* sS = sK + ATK * QSTR;          // ATM*SSTR
    float* sM = sS + ATM * SSTR;          // ATM
    float* sL = sM + ATM;                 // ATM
    float* sC = sL + ATM;                 // ATM

    int side = blockIdx.z;
    const float* Q  = g_h[side];
    const float* KV = g_h[side ^ 1];
    float* O        = g_c[side];

    int t = threadIdx.x;
    int b = blockIdx.y;
    int q0 = blockIdx.x * ATM;
    const float* Qb = Q + (b * NNODES + q0) * DH;
    const float* Kb = KV + b * NNODES * DH;

    // load Q tile (float2)
    for (int i = t; i < ATM * 100; i += 256) {
        int r = i / 100, p = i % 100;
        *reinterpret_cast<float2*>(&sQ[r * QSTR + 2 * p]) =
            reinterpret_cast<const float2*>(Qb)[r * 100 + p];
    }
    if (t < ATM) { sM[t] = -1e30f; sL[t] = 0.f; }

    int w = t / 32, l = t % 32;
    int ty = t / 16, tx = t % 16;
    ull Ov2[8][4];
#pragma unroll
    for (int r = 0; r < 8; r++)
#pragma unroll
        for (int i = 0; i < 4; i++) Ov2[r][i] = 0ull;
    __syncthreads();

    const float* qb[4];
    const float* kb[4];
#pragma unroll
    for (int j = 0; j < 4; j++) qb[j] = sQ + (ty + 16 * j) * QSTR;
#pragma unroll
    for (int i = 0; i < 4; i++) kb[i] = sK + (tx + 16 * i) * QSTR;

    for (int kt = 0; kt < NNODES / ATK; kt++) {
        for (int i = t; i < ATK * 100; i += 256) {
            int r = i / 100, p = i % 100;
            *reinterpret_cast<float2*>(&sK[r * QSTR + 2 * p]) =
                reinterpret_cast<const float2*>(Kb)[(kt * ATK + r) * 100 + p];
        }
        __syncthreads();

        // S tile: thread (ty,tx) owns rows ty+16j, cols tx+16i -- packed FMA over d pairs
        ull sa2[4][4];
#pragma unroll
        for (int j = 0; j < 4; j++)
#pragma unroll
            for (int i = 0; i < 4; i++) sa2[j][i] = 0ull;
#pragma unroll 2
        for (int dp = 0; dp < 100; dp++) {
            ull q2[4], k2[4];
#pragma unroll
            for (int j = 0; j < 4; j++) q2[j] = ld2s(qb[j] + 2 * dp);
#pragma unroll
            for (int i = 0; i < 4; i++) k2[i] = ld2s(kb[i] + 2 * dp);
#pragma unroll
            for (int j = 0; j < 4; j++)
#pragma unroll
                for (int i = 0; i < 4; i++) sa2[j][i] = fma2(q2[j], k2[i], sa2[j][i]);
        }
#pragma unroll
        for (int j = 0; j < 4; j++)
#pragma unroll
            for (int i = 0; i < 4; i++) {
                float2 f = unp2(sa2[j][i]);
                sS[(ty + 16 * j) * SSTR + tx + 16 * i] = (f.x + f.y) * TSCALE;
            }
        __syncthreads();

        // online softmax: 4 threads per row
        {
            int r = t / 4, part = t % 4;
            float mx = -1e30f;
            for (int c = part * 16; c < part * 16 + 16; c++)
                mx = fmaxf(mx, sS[r * SSTR + c]);
            mx = fmaxf(mx, __shfl_xor_sync(0xffffffffu, mx, 1));
            mx = fmaxf(mx, __shfl_xor_sync(0xffffffffu, mx, 2));
            float m_old = sM[r];
            float m_new = fmaxf(m_old, mx);
            float lsum = 0.f;
            for (int c = part * 16; c < part * 16 + 16; c++) {
                float p = __expf(sS[r * SSTR + c] - m_new);
                sS[r * SSTR + c] = p;
                lsum += p;
            }
            lsum += __shfl_xor_sync(0xffffffffu, lsum, 1);
            lsum += __shfl_xor_sync(0xffffffffu, lsum, 2);
            if (part == 0) {
                float corr = __expf(m_old - m_new);
                sC[r] = corr;
                sL[r] = sL[r] * corr + lsum;
                sM[r] = m_new;
            }
        }
        __syncthreads();

        // rescale + PV (packed): warp w owns rows w*8..w*8+7, lane covers d pairs p=l+32i
#pragma unroll
        for (int r = 0; r < 8; r++) {
            ull corr2 = pack2(sC[w * 8 + r], sC[w * 8 + r]);
#pragma unroll
            for (int i = 0; i < 4; i++) Ov2[r][i] = mul2(Ov2[r][i], corr2);
        }
        for (int c = 0; c < ATK; c++) {
            ull vv[4];
#pragma unroll
            for (int i = 0; i < 3; i++) vv[i] = ld2s(&sK[c * QSTR + 2 * (l + 32 * i)]);
            vv[3] = (l < 4) ? ld2s(&sK[c * QSTR + 2 * (l + 96)]) : 0ull;
#pragma unroll
            for (int r = 0; r < 8; r++) {
                float pr = sS[(w * 8 + r) * SSTR + c];
                ull p2 = pack2(pr, pr);
#pragma unroll
                for (int i = 0; i < 4; i++) Ov2[r][i] = fma2(p2, vv[i], Ov2[r][i]);
            }
        }
        __syncthreads();
    }

    float* Ob = O + (b * NNODES + q0) * DH;
#pragma unroll
    for (int r = 0; r < 8; r++) {
        float inv = 1.0f / sL[w * 8 + r];
        int row = w * 8 + r;
#pragma unroll
        for (int i = 0; i < 4; i++) {
            int p = l + 32 * i;
            if (p < 100) {
                float2 f = unp2(Ov2[r][i]);
                reinterpret_cast<float2*>(Ob + row * DH)[p] =
                    make_float2(f.x * inv, f.y * inv);
            }
        }
    }
}

// ---------------- down projection: relu([h||c] @ W_down) + degree_table ----------------
__global__ void __launch_bounds__(256) k_down(const float* __restrict__ Wd,
                                              const float* __restrict__ dtab) {
    extern __shared__ float sm[];
    float* sA = sm;              // 64*51
    float* sB = sm + 64 * 51;    // 50*202
    int side = blockIdx.y;
    const float* h = g_h[side];
    const float* c = g_c[side];
    const int* deg = g_deg[side];
    float* out = g_hf[side];

    int t = threadIdx.x, w = t / 32, l = t % 32;
    int n0 = blockIdx.x * 64;
    ull acc2[8][4];
#pragma unroll
    for (int r = 0; r < 8; r++)
#pragma unroll
        for (int i = 0; i < 4; i++) acc2[r][i] = 0ull;

    for (int ch = 0; ch < 8; ch++) {
        int k0 = ch * 50;
        for (int i = t; i < 64 * 50; i += 256) {
            int r = i / 50, kk = i % 50;
            int j = k0 + kk;
            float vv = (j < DH) ? h[(n0 + r) * DH + j] : c[(n0 + r) * DH + j - DH];
            sA[r * 51 + kk] = vv;
        }
        for (int i = t; i < 50 * 100; i += 256) {
            int kk = i / 100, p = i % 100;
            *reinterpret_cast<float2*>(&sB[kk * QSTR + 2 * p]) =
                reinterpret_cast<const float2*>(Wd)[(k0 + kk) * 100 + p];
        }
        __syncthreads();
        for (int kk = 0; kk < 50; kk++) {
            ull bv[4];
#pragma unroll
            for (int i = 0; i < 3; i++) bv[i] = ld2s(&sB[kk * QSTR + 2 * (l + 32 * i)]);
            bv[3] = (l < 4) ? ld2s(&sB[kk * QSTR + 2 * (l + 96)]) : 0ull;
#pragma unroll
            for (int r = 0; r < 8; r++) {
                float a = sA[(w * 8 + r) * 51 + kk];
                ull a2 = pack2(a, a);
#pragma unroll
                for (int i = 0; i < 4; i++) acc2[r][i] = fma2(a2, bv[i], acc2[r][i]);
            }
        }
        __syncthreads();
    }
#pragma unroll
    for (int r = 0; r < 8; r++) {
        int node = n0 + w * 8 + r;
        int dg = deg[node];
#pragma unroll
        for (int i = 0; i < 4; i++) {
            int p = l + 32 * i;
            if (p < 100) {
                float2 f = unp2(acc2[r][i]);
                float2 dt = reinterpret_cast<const float2*>(dtab + dg * DH)[p];
                reinterpret_cast<float2*>(out + node * DH)[p] =
                    make_float2(fmaxf(f.x, 0.f) + dt.x, fmaxf(f.y, 0.f) + dt.y);
            }
        }
    }
}

// ---------------- fused readout: means -> MLP ----------------
__global__ void __launch_bounds__(256) k_readout(
        const float* __restrict__ i1, const float* __restrict__ i2,
        const float* __restrict__ W1, const float* __restrict__ b1,
        const float* __restrict__ W2, const float* __restrict__ b2,
        const float* __restrict__ W3, const float* __restrict__ b3,
        const float* __restrict__ W4, const float* __restrict__ b4,
        float* __restrict__ out) {
    __shared__ float sx[618], s1[400], s2[200], s3[104];
    int b = blockIdx.x, t = threadIdx.x;
    if (t < DH) {
        float m1 = 0.f, m2 = 0.f;
        const float* p1 = &g_hf[0][b * NNODES * DH + t];
        const float* p2 = &g_hf[1][b * NNODES * DH + t];
#pragma unroll 4
        for (int n = 0; n < NNODES; n++) {
            m1 += p1[n * DH];
            m2 += p2[n * DH];
        }
        m1 *= (1.0f / NNODES); m2 *= (1.0f / NNODES);
        sx[t] = m1; sx[206 + t] = m2; sx[412 + t] = m1 - m2;
    } else if (t < DH + DI) {
        int j = t - DH;
        float m1 = 0.f, m2 = 0.f;
#pragma unroll 4
        for (int n = 0; n < NNODES; n++) {
            m1 += i1[(b * NNODES + n) * DI + j];
            m2 += i2[(b * NNODES + n) * DI + j];
        }
        m1 *= (1.0f / NNODES); m2 *= (1.0f / NNODES);
        sx[200 + j] = m1; sx[406 + j] = m2; sx[612 + j] = m1 - m2;
    }
    __syncthreads();
    for (int o = t; o < 400; o += 256) {
        float a = b1[o];
        for (int j = 0; j < 618; j++) a = fmaf(sx[j], W1[j * 400 + o], a);
        s1[o] = fmaxf(a, 0.f);
    }
    __syncthreads();
    for (int o = t; o < 200; o += 256) {
        float a = b2[o];
        for (int j = 0; j < 400; j++) a = fmaf(s1[j], W2[j * 200 + o], a);
        s2[o] = fmaxf(a, 0.f);
    }
    __syncthreads();
    for (int o = t; o < 100; o += 256) {
        float a = b3[o];
        for (int j = 0; j < 200; j++) a = fmaf(s2[j], W3[j * 100 + o], a);
        s3[o] = fmaxf(a, 0.f);
    }
    __syncthreads();
    if (t < 32) {
        float a = 0.f;
        for (int j = t; j < 100; j += 32) a = fmaf(s3[j], W4[j], a);
#pragma unroll
        for (int o = 16; o > 0; o >>= 1) a += __shfl_xor_sync(0xffffffffu, a, o);
        if (t == 0) out[b] = a + b4[0];
    }
}

// ---------------- launch ----------------
extern "C" void kernel_launch(void* const* d_in, const int* in_sizes, int n_in,
                              void* d_out, int out_size) {
    const float* atom1  = (const float*)d_in[0];
    const float* atom2  = (const float*)d_in[1];
    const float* coords1 = (const float*)d_in[2];
    const float* coords2 = (const float*)d_in[3];
    const float* ef1    = (const float*)d_in[4];
    const float* ef2    = (const float*)d_in[5];
    const float* int1   = (const float*)d_in[6];
    const float* int2   = (const float*)d_in[7];
    const int*   src1   = (const int*)d_in[8];
    const int*   dst1   = (const int*)d_in[9];
    const int*   src2   = (const int*)d_in[10];
    const int*   dst2   = (const int*)d_in[11];
    const float* W_atom = (const float*)d_in[12];
    const float* W_edge = (const float*)d_in[13];
    const float* W_rbf  = (const float*)d_in[14];
    const float* b_rbf  = (const float*)d_in[15];
    const float* ln_g   = (const float*)d_in[16];
    const float* ln_b   = (const float*)d_in[17];
    const float* W_down = (const float*)d_in[18];
    const float* dtab   = (const float*)d_in[19];
    const float* W_f1   = (const float*)d_in[20];
    const float* b_f1   = (const float*)d_in[21];
    const float* W_f2   = (const float*)d_in[22];
    const float* b_f2   = (const float*)d_in[23];
    const float* W_f3   = (const float*)d_in[24];
    const float* b_f3   = (const float*)d_in[25];
    const float* W_f4   = (const float*)d_in[26];
    const float* b_f4   = (const float*)d_in[27];
    float* out = (float*)d_out;

    const int SMEM_ATOM = (DA * DH + 8 * 2 * DA) * 4;
    const int SMEM_ATTN = (ATM * QSTR + ATK * QSTR + ATM * SSTR + 3 * ATM) * 4;
    const int SMEM_DOWN = (64 * 51 + 50 * QSTR) * 4;

    cudaFuncSetAttribute(k_atom, cudaFuncAttributeMaxDynamicSharedMemorySize, SMEM_ATOM);
    cudaFuncSetAttribute(k_attn, cudaFuncAttributeMaxDynamicSharedMemorySize, SMEM_ATTN);
    cudaFuncSetAttribute(k_down, cudaFuncAttributeMaxDynamicSharedMemorySize, SMEM_DOWN);

    // 1: atom GEMM + layernorm (also zeroes CSR counters)
    dim3 gatom(BN / 32, 2);
    k_atom<<<gatom, 256, SMEM_ATOM>>>(atom1, atom2, W_atom, ln_g, ln_b);
    // 2-4: CSR build (both sides fused)
    dim3 gedge(EE / 256, 2);
    k_count<<<gedge, 256>>>(dst1, dst2);
    k_scan<<<2, 1024>>>();
    k_fill<<<gedge, 256>>>(dst1, dst2);
    // 5: edge message gather
    dim3 ggath(512, 2);
    k_gather<<<ggath, 128>>>(ef1, ef2, coords1, coords2, src1, src2,
                             W_edge, W_rbf, b_rbf, ln_g, ln_b);
    // 6: bidirectional cross attention (both sides fused)
    dim3 agrid(NNODES / ATM, BB, 2);
    k_attn<<<agrid, 256, SMEM_ATTN>>>();
    // 7: down projection + degree embedding
    dim3 gdown(BN / 64, 2);
    k_down<<<gdown, 256, SMEM_DOWN>>>(W_down, dtab);
    // 8: fused readout
    k_readout<<<BB, 256>>>(int1, int2, W_f1, b_f1, W_f2, b_f2,
                           W_f3, b_f3, W_f4, b_f4, out);
}

// round 3
// speedup vs baseline: 1.5110x; 1.1026x over previous
#include <cuda_runtime.h>
#include <math.h>

#define BB 64
#define NNODES 512
#define BN 32768
#define EE 524288
#define DA 70
#define DE 14
#define DH 200
#define DI 6
#define DC 16
#define TSCALE 0.07071067811865475f

typedef unsigned long long ull;

// ---------------- f32x2 packed-FMA helpers ----------------
__device__ __forceinline__ ull fma2(ull a, ull b, ull c) {
    ull d;
    asm("fma.rn.f32x2 %0, %1, %2, %3;" : "=l"(d) : "l"(a), "l"(b), "l"(c));
    return d;
}
__device__ __forceinline__ ull mul2(ull a, ull b) {
    ull d;
    asm("mul.rn.f32x2 %0, %1, %2;" : "=l"(d) : "l"(a), "l"(b));
    return d;
}
__device__ __forceinline__ ull pack2(float x, float y) {
    ull r;
    asm("mov.b64 %0, {%1, %2};" : "=l"(r) : "f"(x), "f"(y));
    return r;
}
__device__ __forceinline__ float2 unp2(ull a) {
    float2 f;
    asm("mov.b64 {%0, %1}, %2;" : "=f"(f.x), "=f"(f.y) : "l"(a));
    return f;
}
__device__ __forceinline__ ull ld2s(const float* p) {
    return *reinterpret_cast<const ull*>(p);
}

// ---------------- device scratch ----------------
__device__ float g_h[2][BN * DH];
__device__ int   g_deg[2][BN];
__device__ int   g_cnt[2][BN];      // zero-initialized at load; re-zeroed by k_fill
__device__ int   g_rowptr[2][BN + 1];
__device__ int   g_cursor[2][BN];
__device__ int   g_eidx[2][EE];
__device__ float g_part[2][BB][8][DH];

// ---------------- CSR build ----------------
__global__ void k_count(const int* __restrict__ d1, const int* __restrict__ d2) {
    int side = blockIdx.y;
    const int* dst = side ? d2 : d1;
    int e = blockIdx.x * blockDim.x + threadIdx.x;
    if (e < EE) atomicAdd(&g_cnt[side][dst[e]], 1);
}

__global__ void k_scan() {   // grid=2, 1024 threads
    int side = blockIdx.x;
    __shared__ int ws[32];
    int t = threadIdx.x;
    int base = t * 32;
    int loc[32];
    int sum = 0;
#pragma unroll
    for (int i = 0; i < 32; i++) { loc[i] = g_cnt[side][base + i]; sum += loc[i]; }
    int l = t & 31, w = t >> 5;
    int v = sum;
#pragma unroll
    for (int off = 1; off < 32; off <<= 1) {
        int n = __shfl_up_sync(0xffffffffu, v, off);
        if (l >= off) v += n;
    }
    if (l == 31) ws[w] = v;
    __syncthreads();
    if (w == 0) {
        int x = ws[l];
#pragma unroll
        for (int off = 1; off < 32; off <<= 1) {
            int n = __shfl_up_sync(0xffffffffu, x, off);
            if (l >= off) x += n;
        }
        ws[l] = x;
    }
    __syncthreads();
    int excl = v - sum + (w > 0 ? ws[w - 1] : 0);
    int run = excl;
    for (int i = 0; i < 32; i++) {
        g_rowptr[side][base + i] = run;
        g_cursor[side][base + i] = run;
        run += loc[i];
    }
    if (t == 1023) g_rowptr[side][BN] = run;
}

__global__ void k_fill(const int* __restrict__ d1, const int* __restrict__ d2) {
    int side = blockIdx.y;
    const int* dst = side ? d2 : d1;
    int e = blockIdx.x * blockDim.x + threadIdx.x;
    // re-zero counters for the next graph replay (scan has already consumed them)
    if (e < BN) g_cnt[side][e] = 0;
    if (e < EE) {
        int slot = atomicAdd(&g_cursor[side][dst[e]], 1);
        g_eidx[side][slot] = e;
    }
}

// ---------------- fused atom GEMM+LN + edge-message gather ----------------
__global__ void __launch_bounds__(128) k_gather(
        const float* __restrict__ a1, const float* __restrict__ a2,
        const float* __restrict__ ef1, const float* __restrict__ ef2,
        const float* __restrict__ co1, const float* __restrict__ co2,
        const int* __restrict__ s1, const int* __restrict__ s2,
        const float* __restrict__ W_atom,
        const float* __restrict__ W_edge,
        const float* __restrict__ W_rbf,
        const float* __restrict__ b_rbf,
        const float* __restrict__ lng, const float* __restrict__ lnb) {
    extern __shared__ float sm[];                 // W_atom: 70*200 floats
    __shared__ __align__(16) float s_ef[4][2][16];
    __shared__ __align__(16) float s_rbf[4][2][16];
    __shared__ float s_at[4][70];
    __shared__ __align__(16) float2 sW3[8][32];   // mixed slice i=3 (k=96..127), packed over j

    int side = blockIdx.y;
    const float* atom   = side ? a2 : a1;
    const float* ef     = side ? ef2 : ef1;
    const float* coords = side ? co2 : co1;
    const int*   esrc   = side ? s2 : s1;
    const int*   eidx   = g_eidx[side];
    float* h = g_h[side];
    int t = threadIdx.x, w = t >> 5, l = t & 31;

    for (int i = t; i < (DA * DH) / 2; i += 128)
        reinterpret_cast<float2*>(sm)[i] = reinterpret_cast<const float2*>(W_atom)[i];
    for (int i = t; i < 256; i += 128) {
        int j2 = i >> 5, ll = i & 31;
        int ja = 2 * j2, jb = 2 * j2 + 1;
        float w0, w1;
        if (ll < 4) {
            w0 = (ja < DE) ? W_edge[ja * 100 + 96 + ll] : 0.f;
            w1 = (jb < DE) ? W_edge[jb * 100 + 96 + ll] : 0.f;
        } else {
            w0 = W_rbf[ja * 100 + ll - 4];
            w1 = W_rbf[jb * 100 + ll - 4];
        }
        sW3[j2][ll] = make_float2(w0, w1);
    }
    if (l < 2) { s_ef[w][0][14 + l] = 0.f; s_ef[w][1][14 + l] = 0.f; }

    // per-lane packed weight registers
    ull We2[3][7];       // i = 0..2 (k = l, l+32, l+64)
    ull Wr2[3][8];       // i = 4..6 (kk = l+28, l+60, l+92)
    float brr[3];
    bool val6 = (l < 8); // i=6 valid only for k=192..199
#pragma unroll
    for (int ii = 0; ii < 3; ii++) {
        int k = l + 32 * ii;
#pragma unroll
        for (int j2 = 0; j2 < 7; j2++)
            We2[ii][j2] = pack2(W_edge[(2 * j2) * 100 + k], W_edge[(2 * j2 + 1) * 100 + k]);
    }
#pragma unroll
    for (int ii = 0; ii < 3; ii++) {
        int kk = l + 28 + 32 * ii;
        bool v = (kk < 100);
        brr[ii] = v ? b_rbf[kk] : 0.f;
#pragma unroll
        for (int j2 = 0; j2 < 8; j2++)
            Wr2[ii][j2] = v ? pack2(W_rbf[(2 * j2) * 100 + kk], W_rbf[(2 * j2 + 1) * 100 + kk]) : 0ull;
    }
    float br3 = (l < 4) ? 0.f : b_rbf[l - 4];
    float lg[7], lb[7];
#pragma unroll
    for (int i = 0; i < 7; i++) {
        int k = l + 32 * i;
        bool v = (k < DH);
        lg[i] = v ? lng[k] : 0.f;
        lb[i] = v ? lnb[k] : 0.f;
    }
    __syncthreads();

    int wg = blockIdx.x * 4 + w;
    int nw = gridDim.x * 4;
    for (int node = wg; node < BN; node += nw) {
        // ---- atom GEMM + relu + LN (accumulator stays in registers) ----
        for (int j = l; j < DA; j += 32) s_at[w][j] = atom[node * DA + j];
        __syncwarp();
        float acc[7];
#pragma unroll
        for (int i = 0; i < 7; i++) acc[i] = 0.f;
        for (int j = 0; j < DA; j++) {
            float xa = s_at[w][j];
            const float* wrow = sm + j * DH + l;
#pragma unroll
            for (int i = 0; i < 6; i++) acc[i] = fmaf(xa, wrow[32 * i], acc[i]);
            if (val6) acc[6] = fmaf(xa, wrow[192], acc[6]);
        }
        {
            float s = 0.f, s2v = 0.f;
#pragma unroll
            for (int i = 0; i < 7; i++) {
                float x = fmaxf(acc[i], 0.f);
                if (i == 6 && !val6) x = 0.f;
                acc[i] = x; s += x; s2v += x * x;
            }
#pragma unroll
            for (int o = 16; o > 0; o >>= 1) {
                s += __shfl_xor_sync(0xffffffffu, s, o);
                s2v += __shfl_xor_sync(0xffffffffu, s2v, o);
            }
            float mean = s * (1.0f / DH);
            float var = s2v * (1.0f / DH) - mean * mean;
            float rs = rsqrtf(var + 1e-5f);
#pragma unroll
            for (int i = 0; i < 7; i++) {
                bool v = (i < 6) || val6;
                acc[i] = v ? (lg[i] * (acc[i] - mean) * rs + lb[i]) : 0.f;
            }
        }

        // ---- edge loop with prefetch ----
        int r0 = g_rowptr[side][node], r1 = g_rowptr[side][node + 1];
        float cdx = coords[node * 3 + 0];
        float cdy = coords[node * 3 + 1];
        float cdz = coords[node * 3 + 2];
        int par = 0;
        int eid = 0, srcn = 0;
        float efv = 0.f, sx = 0.f, sy = 0.f, sz = 0.f;
        if (r0 < r1) {
            eid = eidx[r0]; srcn = esrc[eid];
            efv = (l < DE) ? ef[eid * DE + l] : 0.f;
            sx = coords[srcn * 3 + 0]; sy = coords[srcn * 3 + 1]; sz = coords[srcn * 3 + 2];
        }
        for (int e = r0; e < r1; e++) {
            if (l < DE) s_ef[w][par][l] = efv;
            float dx = sx - cdx, dy = sy - cdy, dz = sz - cdz;
            float dist = sqrtf(dx * dx + dy * dy + dz * dz + 1e-12f);
            if (l < DC) {
                float u = (dist - (float)l * (5.0f / 15.0f)) * 3.2f;
                s_rbf[w][par][l] = __expf(-u * u);
            }
            __syncwarp();
            if (e + 1 < r1) {
                eid = eidx[e + 1]; srcn = esrc[eid];
                efv = (l < DE) ? ef[eid * DE + l] : 0.f;
                sx = coords[srcn * 3 + 0]; sy = coords[srcn * 3 + 1]; sz = coords[srcn * 3 + 2];
            }
            ull eE[8], eR[8];
#pragma unroll
            for (int j2 = 0; j2 < 8; j2++) {
                eE[j2] = ld2s(&s_ef[w][par][2 * j2]);
                eR[j2] = ld2s(&s_rbf[w][par][2 * j2]);
            }
            float v[7];
#pragma unroll
            for (int ii = 0; ii < 3; ii++) {
                ull pa = 0ull;
#pragma unroll
                for (int j2 = 0; j2 < 7; j2++) pa = fma2(eE[j2], We2[ii][j2], pa);
                float2 f = unp2(pa);
                v[ii] = f.x + f.y;
            }
            {
                ull pa = 0ull;
                bool isE3 = (l < 4);
#pragma unroll
                for (int j2 = 0; j2 < 8; j2++) {
                    ull m = isE3 ? eE[j2] : eR[j2];
                    pa = fma2(m, ld2s(reinterpret_cast<const float*>(&sW3[j2][l])), pa);
                }
                float2 f = unp2(pa);
                v[3] = f.x + f.y + br3;
            }
#pragma unroll
            for (int ii = 0; ii < 3; ii++) {
                ull pa = 0ull;
#pragma unroll
                for (int j2 = 0; j2 < 8; j2++) pa = fma2(eR[j2], Wr2[ii][j2], pa);
                float2 f = unp2(pa);
                v[4 + ii] = f.x + f.y + brr[ii];
            }
            float s = 0.f, s2v = 0.f;
#pragma unroll
            for (int i = 0; i < 7; i++) {
                float x = fmaxf(v[i], 0.f);
                if (i == 6 && !val6) x = 0.f;
                v[i] = x; s += x; s2v += x * x;
            }
#pragma unroll
            for (int o = 16; o > 0; o >>= 1) {
                s += __shfl_xor_sync(0xffffffffu, s, o);
                s2v += __shfl_xor_sync(0xffffffffu, s2v, o);
            }
            float mean = s * (1.0f / DH);
            float var = s2v * (1.0f / DH) - mean * mean;
            float rs = rsqrtf(var + 1e-5f);
#pragma unroll
            for (int i = 0; i < 7; i++) {
                if (i < 6 || val6) acc[i] += lg[i] * (v[i] - mean) * rs + lb[i];
            }
            par ^= 1;
        }
        int d = r1 - r0;
        g_deg[side][node] = d > 199 ? 199 : d;
#pragma unroll
        for (int i = 0; i < 7; i++) {
            int k = l + 32 * i;
            if (k < DH) h[node * DH + k] = acc[i];
        }
        __syncwarp();
    }
}

// ---------------- fused flash cross-attention + down-proj + degree + tile means ----------------
#define ATM 64
#define ATK 64
#define QSTR 202
#define SSTR 65

__global__ void __launch_bounds__(256) k_attn(const float* __restrict__ Wd,
                                              const float* __restrict__ dtab) {
    extern __shared__ float sm[];
    float* sQ = sm;                       // ATM*QSTR  (h rows, full 200 dims)
    float* sK = sQ + ATM * QSTR;          // ATK*QSTR  (K tile; later c tile)
    float* sS = sK + ATK * QSTR;          // ATM*SSTR  (S; later W chunks; later psums)
    float* sM = sS + ATM * SSTR;
    float* sL = sM + ATM;
    float* sC = sL + ATM;

    int side = blockIdx.z, b = blockIdx.y, qx = blockIdx.x;
    const float* Q  = g_h[side];
    const float* KV = g_h[side ^ 1];
    int t = threadIdx.x, w = t >> 5, l = t & 31;
    int ty = t >> 4, tx = t & 15;
    int q0 = qx * ATM;
    const float* Qb = Q + (b * NNODES + q0) * DH;
    const float* Kb = KV + b * NNODES * DH;

    for (int i = t; i < ATM * 100; i += 256) {
        int r = i / 100, p = i % 100;
        *reinterpret_cast<float2*>(&sQ[r * QSTR + 2 * p]) =
            reinterpret_cast<const float2*>(Qb)[r * 100 + p];
    }
    if (t < ATM) { sM[t] = -1e30f; sL[t] = 0.f; }

    ull Ov[4][7];
#pragma unroll
    for (int j = 0; j < 4; j++)
#pragma unroll
        for (int i = 0; i < 7; i++) Ov[j][i] = 0ull;
    __syncthreads();

    const float* qb[4];
    const float* kb[4];
#pragma unroll
    for (int j = 0; j < 4; j++) qb[j] = sQ + (ty + 16 * j) * QSTR;
#pragma unroll
    for (int i = 0; i < 4; i++) kb[i] = sK + (tx + 16 * i) * QSTR;

    for (int kt = 0; kt < NNODES / ATK; kt++) {
        for (int i = t; i < ATK * 100; i += 256) {
            int r = i / 100, p = i % 100;
            *reinterpret_cast<float2*>(&sK[r * QSTR + 2 * p]) =
                reinterpret_cast<const float2*>(Kb)[(kt * ATK + r) * 100 + p];
        }
        __syncthreads();

        // S = Q K^T (4x4 register tile, packed over d)
        ull sa2[4][4];
#pragma unroll
        for (int j = 0; j < 4; j++)
#pragma unroll
            for (int i = 0; i < 4; i++) sa2[j][i] = 0ull;
#pragma unroll 2
        for (int dp = 0; dp < 100; dp++) {
            ull q2[4], k2[4];
#pragma unroll
            for (int j = 0; j < 4; j++) q2[j] = ld2s(qb[j] + 2 * dp);
#pragma unroll
            for (int i = 0; i < 4; i++) k2[i] = ld2s(kb[i] + 2 * dp);
#pragma unroll
            for (int j = 0; j < 4; j++)
#pragma unroll
                for (int i = 0; i < 4; i++) sa2[j][i] = fma2(q2[j], k2[i], sa2[j][i]);
        }
#pragma unroll
        for (int j = 0; j < 4; j++)
#pragma unroll
            for (int i = 0; i < 4; i++) {
                float2 f = unp2(sa2[j][i]);
                sS[(ty + 16 * j) * SSTR + tx + 16 * i] = (f.x + f.y) * TSCALE;
            }
        __syncthreads();

        // online softmax (4 threads per row)
        {
            int r = t / 4, part = t % 4;
            float mx = -1e30f;
            for (int c = part * 16; c < part * 16 + 16; c++)
                mx = fmaxf(mx, sS[r * SSTR + c]);
            mx = fmaxf(mx, __shfl_xor_sync(0xffffffffu, mx, 1));
            mx = fmaxf(mx, __shfl_xor_sync(0xffffffffu, mx, 2));
            float m_old = sM[r];
            float m_new = fmaxf(m_old, mx);
            float lsum = 0.f;
            for (int c = part * 16; c < part * 16 + 16; c++) {
                float p = __expf(sS[r * SSTR + c] - m_new);
                sS[r * SSTR + c] = p;
                lsum += p;
            }
            lsum += __shfl_xor_sync(0xffffffffu, lsum, 1);
            lsum += __shfl_xor_sync(0xffffffffu, lsum, 2);
            if (part == 0) {
                float corr = __expf(m_old - m_new);
                sC[r] = corr;
                sL[r] = sL[r] * corr + lsum;
                sM[r] = m_new;
            }
        }
        __syncthreads();

        // rescale + PV (rows ty+16j, dpairs tx+16i)
#pragma unroll
        for (int j = 0; j < 4; j++) {
            float cr = sC[ty + 16 * j];
            ull c2 = pack2(cr, cr);
#pragma unroll
            for (int i = 0; i < 7; i++) Ov[j][i] = mul2(Ov[j][i], c2);
        }
        for (int c = 0; c < ATK; c++) {
            ull vv[7];
#pragma unroll
            for (int i = 0; i < 6; i++) vv[i] = ld2s(&sK[c * QSTR + 2 * (tx + 16 * i)]);
            vv[6] = (tx < 4) ? ld2s(&sK[c * QSTR + 2 * (tx + 96)]) : 0ull;
            ull p2[4];
#pragma unroll
            for (int j = 0; j < 4; j++) {
                float pv = sS[(ty + 16 * j) * SSTR + c];
                p2[j] = pack2(pv, pv);
            }
#pragma unroll
            for (int j = 0; j < 4; j++)
#pragma unroll
                for (int i = 0; i < 7; i++) Ov[j][i] = fma2(p2[j], vv[i], Ov[j][i]);
        }
        __syncthreads();
    }

    // normalized attention output c -> sK (reuse)
#pragma unroll
    for (int j = 0; j < 4; j++) {
        int row = ty + 16 * j;
        float inv = 1.0f / sL[row];
        ull inv2 = pack2(inv, inv);
#pragma unroll
        for (int i = 0; i < 7; i++) {
            int p = tx + 16 * i;
            if (p < 100)
                *reinterpret_cast<ull*>(&sK[row * QSTR + 2 * p]) = mul2(Ov[j][i], inv2);
        }
    }

    // ---- down projection: relu([h||c] @ Wd) + dtab[deg]; accumulate tile means ----
    ull acc2[8][4];
#pragma unroll
    for (int r = 0; r < 8; r++)
#pragma unroll
        for (int i = 0; i < 4; i++) acc2[r][i] = 0ull;

    for (int ch = 0; ch < 20; ch++) {
        int k0 = ch * 20;
        __syncthreads();
        for (int idx = t; idx < 20 * 100; idx += 256) {
            int kk = idx / 100, p = idx % 100;
            *reinterpret_cast<float2*>(&sS[kk * QSTR + 2 * p]) =
                reinterpret_cast<const float2*>(Wd)[(k0 + kk) * 100 + p];
        }
        __syncthreads();
        const float* Asrc = (ch < 10) ? sQ : sK;
        int kb2 = (ch < 10) ? k0 : k0 - 200;
        for (int kk = 0; kk < 20; kk++) {
            ull bv[4];
#pragma unroll
            for (int i = 0; i < 3; i++) bv[i] = ld2s(&sS[kk * QSTR + 2 * (l + 32 * i)]);
            bv[3] = (l < 4) ? ld2s(&sS[kk * QSTR + 2 * (l + 96)]) : 0ull;
#pragma unroll
            for (int r = 0; r < 8; r++) {
                float a = Asrc[(w * 8 + r) * QSTR + kb2 + kk];
                ull a2 = pack2(a, a);
#pragma unroll
                for (int i = 0; i < 4; i++) acc2[r][i] = fma2(a2, bv[i], acc2[r][i]);
            }
        }
    }
    __syncthreads();

    ull ps[4];
#pragma unroll
    for (int i = 0; i < 4; i++) ps[i] = 0ull;
#pragma unroll
    for (int r = 0; r < 8; r++) {
        int gnode = b * NNODES + q0 + w * 8 + r;
        int dg = g_deg[side][gnode];
#pragma unroll
        for (int i = 0; i < 4; i++) {
            int p = l + 32 * i;
            if (p < 100) {
                float2 f = unp2(acc2[r][i]);
                float2 dt = *reinterpret_cast<const float2*>(&dtab[dg * DH + 2 * p]);
                float hx = fmaxf(f.x, 0.f) + dt.x;
                float hy = fmaxf(f.y, 0.f) + dt.y;
                float2 pp = unp2(ps[i]);
                ps[i] = pack2(pp.x + hx, pp.y + hy);
            }
        }
    }
#pragma unroll
    for (int i = 0; i < 4; i++) {
        int p = l + 32 * i;
        if (p < 100) *reinterpret_cast<ull*>(&sS[w * 200 + 2 * p]) = ps[i];
    }
    __syncthreads();
    if (t < 100) {
        float sxv = 0.f, syv = 0.f;
#pragma unroll
        for (int ww = 0; ww < 8; ww++) {
            float2 a = *reinterpret_cast<float2*>(&sS[ww * 200 + 2 * t]);
            sxv += a.x; syv += a.y;
        }
        *reinterpret_cast<float2*>(&g_part[side][b][qx][2 * t]) = make_float2(sxv, syv);
    }
}

// ---------------- fused readout: means -> MLP ----------------
__global__ void __launch_bounds__(256) k_readout(
        const float* __restrict__ i1, const float* __restrict__ i2,
        const float* __restrict__ W1, const float* __restrict__ b1,
        const float* __restrict__ W2, const float* __restrict__ b2,
        const float* __restrict__ W3, const float* __restrict__ b3,
        const float* __restrict__ W4, const float* __restrict__ b4,
        float* __restrict__ out) {
    __shared__ float sx[618], s1[400], s2[200], s3[104];
    int b = blockIdx.x, t = threadIdx.x;
    if (t < DH) {
        float m1 = 0.f, m2 = 0.f;
#pragma unroll
        for (int tile = 0; tile < 8; tile++) {
            m1 += g_part[0][b][tile][t];
            m2 += g_part[1][b][tile][t];
        }
        m1 *= (1.0f / NNODES); m2 *= (1.0f / NNODES);
        sx[t] = m1; sx[206 + t] = m2; sx[412 + t] = m1 - m2;
    } else if (t < DH + DI) {
        int j = t - DH;
        float m1 = 0.f, m2 = 0.f;
#pragma unroll 4
        for (int n = 0; n < NNODES; n++) {
            m1 += i1[(b * NNODES + n) * DI + j];
            m2 += i2[(b * NNODES + n) * DI + j];
        }
        m1 *= (1.0f / NNODES); m2 *= (1.0f / NNODES);
        sx[200 + j] = m1; sx[406 + j] = m2; sx[612 + j] = m1 - m2;
    }
    __syncthreads();
    for (int o = t; o < 400; o += 256) {
        float a = b1[o];
        for (int j = 0; j < 618; j++) a = fmaf(sx[j], W1[j * 400 + o], a);
        s1[o] = fmaxf(a, 0.f);
    }
    __syncthreads();
    for (int o = t; o < 200; o += 256) {
        float a = b2[o];
        for (int j = 0; j < 400; j++) a = fmaf(s1[j], W2[j * 200 + o], a);
        s2[o] = fmaxf(a, 0.f);
    }
    __syncthreads();
    for (int o = t; o < 100; o += 256) {
        float a = b3[o];
        for (int j = 0; j < 200; j++) a = fmaf(s2[j], W3[j * 100 + o], a);
        s3[o] = fmaxf(a, 0.f);
    }
    __syncthreads();
    if (t < 32) {
        float a = 0.f;
        for (int j = t; j < 100; j += 32) a = fmaf(s3[j], W4[j], a);
#pragma unroll
        for (int o = 16; o > 0; o >>= 1) a += __shfl_xor_sync(0xffffffffu, a, o);
        if (t == 0) out[b] = a + b4[0];
    }
}

// ---------------- launch ----------------
extern "C" void kernel_launch(void* const* d_in, const int* in_sizes, int n_in,
                              void* d_out, int out_size) {
    const float* atom1  = (const float*)d_in[0];
    const float* atom2  = (const float*)d_in[1];
    const float* coords1 = (const float*)d_in[2];
    const float* coords2 = (const float*)d_in[3];
    const float* ef1    = (const float*)d_in[4];
    const float* ef2    = (const float*)d_in[5];
    const float* int1   = (const float*)d_in[6];
    const float* int2   = (const float*)d_in[7];
    const int*   src1   = (const int*)d_in[8];
    const int*   dst1   = (const int*)d_in[9];
    const int*   src2   = (const int*)d_in[10];
    const int*   dst2   = (const int*)d_in[11];
    const float* W_atom = (const float*)d_in[12];
    const float* W_edge = (const float*)d_in[13];
    const float* W_rbf  = (const float*)d_in[14];
    const float* b_rbf  = (const float*)d_in[15];
    const float* ln_g   = (const float*)d_in[16];
    const float* ln_b   = (const float*)d_in[17];
    const float* W_down = (const float*)d_in[18];
    const float* dtab   = (const float*)d_in[19];
    const float* W_f1   = (const float*)d_in[20];
    const float* b_f1   = (const float*)d_in[21];
    const float* W_f2   = (const float*)d_in[22];
    const float* b_f2   = (const float*)d_in[23];
    const float* W_f3   = (const float*)d_in[24];
    const float* b_f3   = (const float*)d_in[25];
    const float* W_f4   = (const float*)d_in[26];
    const float* b_f4   = (const float*)d_in[27];
    float* out = (float*)d_out;

    const int SMEM_GATHER = DA * DH * 4;                                           // 56000
    const int SMEM_ATTN = (ATM * QSTR + ATK * QSTR + ATM * SSTR + 3 * ATM) * 4;    // 120832

    cudaFuncSetAttribute(k_gather, cudaFuncAttributeMaxDynamicSharedMemorySize, SMEM_GATHER);
    cudaFuncSetAttribute(k_attn, cudaFuncAttributeMaxDynamicSharedMemorySize, SMEM_ATTN);

    dim3 gedge(EE / 256, 2);
    // 0-2: CSR build (g_cnt starts zeroed at load; k_fill re-zeroes it each run)
    k_count<<<gedge, 256>>>(dst1, dst2);
    k_scan<<<2, 1024>>>();
    k_fill<<<gedge, 256>>>(dst1, dst2);
    // 3: fused atom GEMM/LN + edge-message gather  (this is the profiled slot)
    dim3 ggath(1024, 2);
    k_gather<<<ggath, 128, SMEM_GATHER>>>(atom1, atom2, ef1, ef2, coords1, coords2,
                                          src1, src2, W_atom, W_edge, W_rbf, b_rbf,
                                          ln_g, ln_b);
    // 4: fused flash cross-attention + down projection + degree + tile means
    dim3 agrid(NNODES / ATM, BB, 2);
    k_attn<<<agrid, 256, SMEM_ATTN>>>(W_down, dtab);
    // 5: fused readout
    k_readout<<<BB, 256>>>(int1, int2, W_f1, b_f1, W_f2, b_f2,
                           W_f3, b_f3, W_f4, b_f4, out);
}

// round 4
// speedup vs baseline: 1.6215x; 1.0731x over previous
#include <cuda_runtime.h>
#include <math.h>

#define BB 64
#define NNODES 512
#define BN 32768
#define EE 524288
#define DA 70
#define DE 14
#define DH 200
#define DI 6
#define DC 16
#define TSCALE 0.07071067811865475f

typedef unsigned long long ull;

// ---------------- f32x2 packed-FMA helpers ----------------
__device__ __forceinline__ ull fma2(ull a, ull b, ull c) {
    ull d;
    asm("fma.rn.f32x2 %0, %1, %2, %3;" : "=l"(d) : "l"(a), "l"(b), "l"(c));
    return d;
}
__device__ __forceinline__ ull mul2(ull a, ull b) {
    ull d;
    asm("mul.rn.f32x2 %0, %1, %2;" : "=l"(d) : "l"(a), "l"(b));
    return d;
}
__device__ __forceinline__ ull pack2(float x, float y) {
    ull r;
    asm("mov.b64 %0, {%1, %2};" : "=l"(r) : "f"(x), "f"(y));
    return r;
}
__device__ __forceinline__ float2 unp2(ull a) {
    float2 f;
    asm("mov.b64 {%0, %1}, %2;" : "=f"(f.x), "=f"(f.y) : "l"(a));
    return f;
}
__device__ __forceinline__ ull ld2s(const float* p) {
    return *reinterpret_cast<const ull*>(p);
}

// ---------------- device scratch ----------------
__device__ float g_h[2][BN * DH];
__device__ int   g_deg[2][BN];
__device__ int   g_cnt[2][BN];      // zeroed at load; re-zeroed by k_fill each run
__device__ int   g_rowptr[2][BN + 1];
__device__ int   g_cursor[2][BN];
__device__ int   g_eidx[2][EE];
__device__ float g_part[2][BB][8][DH];

// ---------------- atom GEMM + LN (also does edge counting) ----------------
__global__ void __launch_bounds__(256) k_atom(const float* __restrict__ a1,
                                              const float* __restrict__ a2,
                                              const int* __restrict__ d1,
                                              const int* __restrict__ d2,
                                              const float* __restrict__ W,
                                              const float* __restrict__ lng,
                                              const float* __restrict__ lnb) {
    extern __shared__ float sm[];
    float* sW = sm;             // DA*DH
    float* sA = sm + DA * DH;   // 8 warps * 2 rows * DA
    int side = blockIdx.y;
    const float* atom = side ? a2 : a1;
    const int* dst = side ? d2 : d1;
    float* out = g_h[side];
    int t = threadIdx.x;

    // fold edge counting in (grid.x=1024, 256 thr -> 2 edges per thread per side)
    {
        int e0 = blockIdx.x * 256 + t;
#pragma unroll
        for (int r = 0; r < 2; r++) {
            int e = e0 + r * 262144;
            atomicAdd(&g_cnt[side][dst[e]], 1);
        }
    }

    for (int i = t; i < DA * DH; i += 256) sW[i] = W[i];
    int w = t / 32, l = t % 32;
    float lg[7], lb[7];
#pragma unroll
    for (int i = 0; i < 7; i++) {
        int k = l + 32 * i;
        lg[i] = (k < DH) ? lng[k] : 0.f;
        lb[i] = (k < DH) ? lnb[k] : 0.f;
    }
    __syncthreads();
    float* myA = sA + w * 2 * DA;
    for (int pair = 0; pair < 2; pair++) {
        int n0 = (blockIdx.x * 8 + w) * 4 + pair * 2;
        for (int j = l; j < 2 * DA; j += 32) myA[j] = atom[n0 * DA + j];
        __syncwarp();
        float a0[7], a1v[7];
#pragma unroll
        for (int i = 0; i < 7; i++) { a0[i] = 0.f; a1v[i] = 0.f; }
        for (int j = 0; j < DA; j++) {
            float x0 = myA[j], x1 = myA[DA + j];
#pragma unroll
            for (int i = 0; i < 7; i++) {
                int k = l + 32 * i;
                if (k < DH) {
                    float wv = sW[j * DH + k];
                    a0[i] = fmaf(x0, wv, a0[i]);
                    a1v[i] = fmaf(x1, wv, a1v[i]);
                }
            }
        }
        // LN + write (node n0, n0+1)
#pragma unroll
        for (int nn = 0; nn < 2; nn++) {
            float* acc = nn ? a1v : a0;
            float s = 0.f, s2v = 0.f;
#pragma unroll
            for (int i = 0; i < 7; i++) {
                int k = l + 32 * i;
                if (k < DH) { float v = fmaxf(acc[i], 0.f); acc[i] = v; s += v; s2v += v * v; }
            }
#pragma unroll
            for (int o = 16; o > 0; o >>= 1) {
                s += __shfl_xor_sync(0xffffffffu, s, o);
                s2v += __shfl_xor_sync(0xffffffffu, s2v, o);
            }
            float m = s * (1.0f / DH);
            float var = s2v * (1.0f / DH) - m * m;
            float rs = rsqrtf(var + 1e-5f);
#pragma unroll
            for (int i = 0; i < 7; i++) {
                int k = l + 32 * i;
                if (k < DH) out[(n0 + nn) * DH + k] = lg[i] * (acc[i] - m) * rs + lb[i];
            }
        }
        __syncwarp();
    }
}

// ---------------- CSR scan + fill ----------------
__global__ void k_scan() {   // grid=2, 1024 threads
    int side = blockIdx.x;
    __shared__ int ws[32];
    int t = threadIdx.x;
    int base = t * 32;
    int loc[32];
    int sum = 0;
#pragma unroll
    for (int i = 0; i < 32; i++) { loc[i] = g_cnt[side][base + i]; sum += loc[i]; }
    int l = t & 31, w = t >> 5;
    int v = sum;
#pragma unroll
    for (int off = 1; off < 32; off <<= 1) {
        int n = __shfl_up_sync(0xffffffffu, v, off);
        if (l >= off) v += n;
    }
    if (l == 31) ws[w] = v;
    __syncthreads();
    if (w == 0) {
        int x = ws[l];
#pragma unroll
        for (int off = 1; off < 32; off <<= 1) {
            int n = __shfl_up_sync(0xffffffffu, x, off);
            if (l >= off) x += n;
        }
        ws[l] = x;
    }
    __syncthreads();
    int excl = v - sum + (w > 0 ? ws[w - 1] : 0);
    int run = excl;
    for (int i = 0; i < 32; i++) {
        g_rowptr[side][base + i] = run;
        g_cursor[side][base + i] = run;
        run += loc[i];
    }
    if (t == 1023) g_rowptr[side][BN] = run;
}

__global__ void k_fill(const int* __restrict__ d1, const int* __restrict__ d2) {
    int side = blockIdx.y;
    const int* dst = side ? d2 : d1;
    int e = blockIdx.x * blockDim.x + threadIdx.x;
    if (e < BN) g_cnt[side][e] = 0;   // re-zero for next replay
    if (e < EE) {
        int slot = atomicAdd(&g_cursor[side][dst[e]], 1);
        g_eidx[side][slot] = e;
    }
}

// ---------------- edge-message gather: h += sum_edges LN([e||r]) ----------------
__global__ void __launch_bounds__(128, 6) k_gather(
        const float* __restrict__ ef1, const float* __restrict__ ef2,
        const float* __restrict__ co1, const float* __restrict__ co2,
        const int* __restrict__ s1, const int* __restrict__ s2,
        const float* __restrict__ W_edge,
        const float* __restrict__ W_rbf,
        const float* __restrict__ b_rbf,
        const float* __restrict__ lng, const float* __restrict__ lnb) {
    __shared__ __align__(16) float2 sWe[7][96];   // k = 0..95, j-pair
    __shared__ __align__(16) float2 sWr[8][96];   // idx = kk-28, kk = 28..123 (0 beyond 99)
    __shared__ __align__(16) float2 sW3[8][32];   // mixed slice k = 96..127
    __shared__ __align__(16) float s_ef[4][2][16];
    __shared__ __align__(16) float s_rbf[4][2][16];

    int side = blockIdx.y;
    const float* ef     = side ? ef2 : ef1;
    const float* coords = side ? co2 : co1;
    const int*   esrc   = side ? s2 : s1;
    const int*   eidx   = g_eidx[side];
    const int*   rowptr = g_rowptr[side];
    float* h = g_h[side];
    int t = threadIdx.x, w = t >> 5, l = t & 31;

    for (int i = t; i < 7 * 96; i += 128) {
        int j2 = i / 96, k = i % 96;
        sWe[j2][k] = make_float2(W_edge[(2 * j2) * 100 + k], W_edge[(2 * j2 + 1) * 100 + k]);
    }
    for (int i = t; i < 8 * 96; i += 128) {
        int j2 = i / 96, idx = i % 96;
        int kk = idx + 28;
        float wa = (kk < 100) ? W_rbf[(2 * j2) * 100 + kk] : 0.f;
        float wb = (kk < 100) ? W_rbf[(2 * j2 + 1) * 100 + kk] : 0.f;
        sWr[j2][idx] = make_float2(wa, wb);
    }
    for (int i = t; i < 8 * 32; i += 128) {
        int j2 = i >> 5, ll = i & 31;
        int ja = 2 * j2, jb = 2 * j2 + 1;
        float w0, w1;
        if (ll < 4) {
            w0 = (ja < DE) ? W_edge[ja * 100 + 96 + ll] : 0.f;
            w1 = (jb < DE) ? W_edge[jb * 100 + 96 + ll] : 0.f;
        } else {
            w0 = W_rbf[ja * 100 + ll - 4];
            w1 = W_rbf[jb * 100 + ll - 4];
        }
        sW3[j2][ll] = make_float2(w0, w1);
    }
    if (l < 2) { s_ef[w][0][14 + l] = 0.f; s_ef[w][1][14 + l] = 0.f; }

    float brr[3];
#pragma unroll
    for (int ii = 0; ii < 3; ii++) {
        int kk = l + 28 + 32 * ii;
        brr[ii] = (kk < 100) ? b_rbf[kk] : 0.f;
    }
    float br3 = (l < 4) ? 0.f : b_rbf[l - 4];
    float lg[7], lb[7];
#pragma unroll
    for (int i = 0; i < 7; i++) {
        int k = l + 32 * i;
        bool v = (k < DH);
        lg[i] = v ? lng[k] : 0.f;
        lb[i] = v ? lnb[k] : 0.f;
    }
    bool val6 = (l < 8);
    __syncthreads();

    int wg = blockIdx.x * 4 + w;
    int nw = gridDim.x * 4;
    for (int node = wg; node < BN; node += nw) {
        int r0 = rowptr[node], r1 = rowptr[node + 1];
        float acc[7];
#pragma unroll
        for (int i = 0; i < 7; i++) {
            int k = l + 32 * i;
            acc[i] = (k < DH) ? h[node * DH + k] : 0.f;
        }
        float cdx = coords[node * 3 + 0];
        float cdy = coords[node * 3 + 1];
        float cdz = coords[node * 3 + 2];
        int par = 0;
        // pipeline: data(e) in regs; indices for e+1 in (eid1, src1)
        int eid1 = 0, src1 = 0;
        float efv = 0.f, sx = 0.f, sy = 0.f, sz = 0.f;
        if (r0 < r1) {
            int eid0 = eidx[r0];
            int src0 = esrc[eid0];
            efv = (l < DE) ? ef[eid0 * DE + l] : 0.f;
            sx = coords[src0 * 3 + 0]; sy = coords[src0 * 3 + 1]; sz = coords[src0 * 3 + 2];
            if (r0 + 1 < r1) { eid1 = eidx[r0 + 1]; src1 = esrc[eid1]; }
        }
        for (int e = r0; e < r1; e++) {
            // stage current edge data
            if (l < DE) s_ef[w][par][l] = efv;
            float dx = sx - cdx, dy = sy - cdy, dz = sz - cdz;
            float dist = sqrtf(dx * dx + dy * dy + dz * dz + 1e-12f);
            if (l < DC) {
                float u = (dist - (float)l * (5.0f / 15.0f)) * 3.2f;
                s_rbf[w][par][l] = __expf(-u * u);
            }
            __syncwarp();
            // issue loads for e+1 (indices already resolved last iteration)
            if (e + 1 < r1) {
                efv = (l < DE) ? ef[eid1 * DE + l] : 0.f;
                sx = coords[src1 * 3 + 0]; sy = coords[src1 * 3 + 1]; sz = coords[src1 * 3 + 2];
            }
            // resolve indices for e+2 (consumed next iteration)
            if (e + 2 < r1) {
                eid1 = eidx[e + 2];
                src1 = esrc[eid1];
            }
            ull eE[8], eR[8];
#pragma unroll
            for (int j2 = 0; j2 < 8; j2++) {
                eE[j2] = ld2s(&s_ef[w][par][2 * j2]);
                eR[j2] = ld2s(&s_rbf[w][par][2 * j2]);
            }
            float v[7];
#pragma unroll
            for (int ii = 0; ii < 3; ii++) {
                ull pa = 0ull;
#pragma unroll
                for (int j2 = 0; j2 < 7; j2++)
                    pa = fma2(eE[j2], ld2s(reinterpret_cast<const float*>(&sWe[j2][l + 32 * ii])), pa);
                float2 f = unp2(pa);
                v[ii] = f.x + f.y;
            }
            {
                ull pa = 0ull;
                bool isE3 = (l < 4);
#pragma unroll
                for (int j2 = 0; j2 < 8; j2++) {
                    ull m = isE3 ? eE[j2] : eR[j2];
                    pa = fma2(m, ld2s(reinterpret_cast<const float*>(&sW3[j2][l])), pa);
                }
                float2 f = unp2(pa);
                v[3] = f.x + f.y + br3;
            }
#pragma unroll
            for (int ii = 0; ii < 3; ii++) {
                ull pa = 0ull;
#pragma unroll
                for (int j2 = 0; j2 < 8; j2++)
                    pa = fma2(eR[j2], ld2s(reinterpret_cast<const float*>(&sWr[j2][l + 32 * ii])), pa);
                float2 f = unp2(pa);
                v[4 + ii] = f.x + f.y + brr[ii];
            }
            float s = 0.f, s2v = 0.f;
#pragma unroll
            for (int i = 0; i < 7; i++) {
                float x = fmaxf(v[i], 0.f);
                if (i == 6 && !val6) x = 0.f;
                v[i] = x; s += x; s2v += x * x;
            }
#pragma unroll
            for (int o = 16; o > 0; o >>= 1) {
                s += __shfl_xor_sync(0xffffffffu, s, o);
                s2v += __shfl_xor_sync(0xffffffffu, s2v, o);
            }
            float mean = s * (1.0f / DH);
            float var = s2v * (1.0f / DH) - mean * mean;
            float rs = rsqrtf(var + 1e-5f);
#pragma unroll
            for (int i = 0; i < 7; i++) {
                if (i < 6 || val6) acc[i] += lg[i] * (v[i] - mean) * rs + lb[i];
            }
            par ^= 1;
        }
        int d = r1 - r0;
        g_deg[side][node] = d > 199 ? 199 : d;
#pragma unroll
        for (int i = 0; i < 7; i++) {
            int k = l + 32 * i;
            if (k < DH) h[node * DH + k] = acc[i];
        }
        __syncwarp();
    }
}

// ---------------- fused flash cross-attention + down-proj + degree + tile means ----------------
#define ATM 64
#define ATK 64
#define QSTR 202
#define SSTR 65

__global__ void __launch_bounds__(256) k_attn(const float* __restrict__ Wd,
                                              const float* __restrict__ dtab) {
    extern __shared__ float sm[];
    float* sQ = sm;                       // ATM*QSTR
    float* sK = sQ + ATM * QSTR;          // ATK*QSTR (K tile; later c tile)
    float* sS = sK + ATK * QSTR;          // ATM*SSTR (S; later W chunks; later psums)
    float* sM = sS + ATM * SSTR;
    float* sL = sM + ATM;
    float* sC = sL + ATM;

    int side = blockIdx.z, b = blockIdx.y, qx = blockIdx.x;
    const float* Q  = g_h[side];
    const float* KV = g_h[side ^ 1];
    int t = threadIdx.x, w = t >> 5, l = t & 31;
    int ty = t >> 4, tx = t & 15;
    int q0 = qx * ATM;
    const float* Qb = Q + (b * NNODES + q0) * DH;
    const float* Kb = KV + b * NNODES * DH;

    for (int i = t; i < ATM * 100; i += 256) {
        int r = i / 100, p = i % 100;
        *reinterpret_cast<float2*>(&sQ[r * QSTR + 2 * p]) =
            reinterpret_cast<const float2*>(Qb)[r * 100 + p];
    }
    if (t < ATM) { sM[t] = -1e30f; sL[t] = 0.f; }

    ull Ov[4][7];
#pragma unroll
    for (int j = 0; j < 4; j++)
#pragma unroll
        for (int i = 0; i < 7; i++) Ov[j][i] = 0ull;
    __syncthreads();

    const float* qb[4];
    const float* kb[4];
#pragma unroll
    for (int j = 0; j < 4; j++) qb[j] = sQ + (ty + 16 * j) * QSTR;
#pragma unroll
    for (int i = 0; i < 4; i++) kb[i] = sK + (tx + 16 * i) * QSTR;

    for (int kt = 0; kt < NNODES / ATK; kt++) {
        for (int i = t; i < ATK * 100; i += 256) {
            int r = i / 100, p = i % 100;
            *reinterpret_cast<float2*>(&sK[r * QSTR + 2 * p]) =
                reinterpret_cast<const float2*>(Kb)[(kt * ATK + r) * 100 + p];
        }
        __syncthreads();

        ull sa2[4][4];
#pragma unroll
        for (int j = 0; j < 4; j++)
#pragma unroll
            for (int i = 0; i < 4; i++) sa2[j][i] = 0ull;
#pragma unroll 2
        for (int dp = 0; dp < 100; dp++) {
            ull q2[4], k2[4];
#pragma unroll
            for (int j = 0; j < 4; j++) q2[j] = ld2s(qb[j] + 2 * dp);
#pragma unroll
            for (int i = 0; i < 4; i++) k2[i] = ld2s(kb[i] + 2 * dp);
#pragma unroll
            for (int j = 0; j < 4; j++)
#pragma unroll
                for (int i = 0; i < 4; i++) sa2[j][i] = fma2(q2[j], k2[i], sa2[j][i]);
        }
#pragma unroll
        for (int j = 0; j < 4; j++)
#pragma unroll
            for (int i = 0; i < 4; i++) {
                float2 f = unp2(sa2[j][i]);
                sS[(ty + 16 * j) * SSTR + tx + 16 * i] = (f.x + f.y) * TSCALE;
            }
        __syncthreads();

        {
            int r = t / 4, part = t % 4;
            float mx = -1e30f;
            for (int c = part * 16; c < part * 16 + 16; c++)
                mx = fmaxf(mx, sS[r * SSTR + c]);
            mx = fmaxf(mx, __shfl_xor_sync(0xffffffffu, mx, 1));
            mx = fmaxf(mx, __shfl_xor_sync(0xffffffffu, mx, 2));
            float m_old = sM[r];
            float m_new = fmaxf(m_old, mx);
            float lsum = 0.f;
            for (int c = part * 16; c < part * 16 + 16; c++) {
                float p = __expf(sS[r * SSTR + c] - m_new);
                sS[r * SSTR + c] = p;
                lsum += p;
            }
            lsum += __shfl_xor_sync(0xffffffffu, lsum, 1);
            lsum += __shfl_xor_sync(0xffffffffu, lsum, 2);
            if (part == 0) {
                float corr = __expf(m_old - m_new);
                sC[r] = corr;
                sL[r] = sL[r] * corr + lsum;
                sM[r] = m_new;
            }
        }
        __syncthreads();

#pragma unroll
        for (int j = 0; j < 4; j++) {
            float cr = sC[ty + 16 * j];
            ull c2 = pack2(cr, cr);
#pragma unroll
            for (int i = 0; i < 7; i++) Ov[j][i] = mul2(Ov[j][i], c2);
        }
        for (int c = 0; c < ATK; c++) {
            ull vv[7];
#pragma unroll
            for (int i = 0; i < 6; i++) vv[i] = ld2s(&sK[c * QSTR + 2 * (tx + 16 * i)]);
            vv[6] = (tx < 4) ? ld2s(&sK[c * QSTR + 2 * (tx + 96)]) : 0ull;
            ull p2[4];
#pragma unroll
            for (int j = 0; j < 4; j++) {
                float pv = sS[(ty + 16 * j) * SSTR + c];
                p2[j] = pack2(pv, pv);
            }
#pragma unroll
            for (int j = 0; j < 4; j++)
#pragma unroll
                for (int i = 0; i < 7; i++) Ov[j][i] = fma2(p2[j], vv[i], Ov[j][i]);
        }
        __syncthreads();
    }

#pragma unroll
    for (int j = 0; j < 4; j++) {
        int row = ty + 16 * j;
        float inv = 1.0f / sL[row];
        ull inv2 = pack2(inv, inv);
#pragma unroll
        for (int i = 0; i < 7; i++) {
            int p = tx + 16 * i;
            if (p < 100)
                *reinterpret_cast<ull*>(&sK[row * QSTR + 2 * p]) = mul2(Ov[j][i], inv2);
        }
    }

    ull acc2[8][4];
#pragma unroll
    for (int r = 0; r < 8; r++)
#pragma unroll
        for (int i = 0; i < 4; i++) acc2[r][i] = 0ull;

    for (int ch = 0; ch < 20; ch++) {
        int k0 = ch * 20;
        __syncthreads();
        for (int idx = t; idx < 20 * 100; idx += 256) {
            int kk = idx / 100, p = idx % 100;
            *reinterpret_cast<float2*>(&sS[kk * QSTR + 2 * p]) =
                reinterpret_cast<const float2*>(Wd)[(k0 + kk) * 100 + p];
        }
        __syncthreads();
        const float* Asrc = (ch < 10) ? sQ : sK;
        int kb2 = (ch < 10) ? k0 : k0 - 200;
        for (int kk = 0; kk < 20; kk++) {
            ull bv[4];
#pragma unroll
            for (int i = 0; i < 3; i++) bv[i] = ld2s(&sS[kk * QSTR + 2 * (l + 32 * i)]);
            bv[3] = (l < 4) ? ld2s(&sS[kk * QSTR + 2 * (l + 96)]) : 0ull;
#pragma unroll
            for (int r = 0; r < 8; r++) {
                float a = Asrc[(w * 8 + r) * QSTR + kb2 + kk];
                ull a2 = pack2(a, a);
#pragma unroll
                for (int i = 0; i < 4; i++) acc2[r][i] = fma2(a2, bv[i], acc2[r][i]);
            }
        }
    }
    __syncthreads();

    ull ps[4];
#pragma unroll
    for (int i = 0; i < 4; i++) ps[i] = 0ull;
#pragma unroll
    for (int r = 0; r < 8; r++) {
        int gnode = b * NNODES + q0 + w * 8 + r;
        int dg = g_deg[side][gnode];
#pragma unroll
        for (int i = 0; i < 4; i++) {
            int p = l + 32 * i;
            if (p < 100) {
                float2 f = unp2(acc2[r][i]);
                float2 dt = *reinterpret_cast<const float2*>(&dtab[dg * DH + 2 * p]);
                float hx = fmaxf(f.x, 0.f) + dt.x;
                float hy = fmaxf(f.y, 0.f) + dt.y;
                float2 pp = unp2(ps[i]);
                ps[i] = pack2(pp.x + hx, pp.y + hy);
            }
        }
    }
#pragma unroll
    for (int i = 0; i < 4; i++) {
        int p = l + 32 * i;
        if (p < 100) *reinterpret_cast<ull*>(&sS[w * 200 + 2 * p]) = ps[i];
    }
    __syncthreads();
    if (t < 100) {
        float sxv = 0.f, syv = 0.f;
#pragma unroll
        for (int ww = 0; ww < 8; ww++) {
            float2 a = *reinterpret_cast<float2*>(&sS[ww * 200 + 2 * t]);
            sxv += a.x; syv += a.y;
        }
        *reinterpret_cast<float2*>(&g_part[side][b][qx][2 * t]) = make_float2(sxv, syv);
    }
}

// ---------------- fused readout ----------------
__global__ void __launch_bounds__(256) k_readout(
        const float* __restrict__ i1, const float* __restrict__ i2,
        const float* __restrict__ W1, const float* __restrict__ b1,
        const float* __restrict__ W2, const float* __restrict__ b2,
        const float* __restrict__ W3, const float* __restrict__ b3,
        const float* __restrict__ W4, const float* __restrict__ b4,
        float* __restrict__ out) {
    __shared__ float sx[618], s1[400], s2[200], s3[104];
    int b = blockIdx.x, t = threadIdx.x;
    if (t < DH) {
        float m1 = 0.f, m2 = 0.f;
#pragma unroll
        for (int tile = 0; tile < 8; tile++) {
            m1 += g_part[0][b][tile][t];
            m2 += g_part[1][b][tile][t];
        }
        m1 *= (1.0f / NNODES); m2 *= (1.0f / NNODES);
        sx[t] = m1; sx[206 + t] = m2; sx[412 + t] = m1 - m2;
    } else if (t < DH + DI) {
        int j = t - DH;
        float m1 = 0.f, m2 = 0.f;
#pragma unroll 4
        for (int n = 0; n < NNODES; n++) {
            m1 += i1[(b * NNODES + n) * DI + j];
            m2 += i2[(b * NNODES + n) * DI + j];
        }
        m1 *= (1.0f / NNODES); m2 *= (1.0f / NNODES);
        sx[200 + j] = m1; sx[406 + j] = m2; sx[612 + j] = m1 - m2;
    }
    __syncthreads();
    for (int o = t; o < 400; o += 256) {
        float a = b1[o];
        for (int j = 0; j < 618; j++) a = fmaf(sx[j], W1[j * 400 + o], a);
        s1[o] = fmaxf(a, 0.f);
    }
    __syncthreads();
    for (int o = t; o < 200; o += 256) {
        float a = b2[o];
        for (int j = 0; j < 400; j++) a = fmaf(s1[j], W2[j * 200 + o], a);
        s2[o] = fmaxf(a, 0.f);
    }
    __syncthreads();
    for (int o = t; o < 100; o += 256) {
        float a = b3[o];
        for (int j = 0; j < 200; j++) a = fmaf(s2[j], W3[j * 100 + o], a);
        s3[o] = fmaxf(a, 0.f);
    }
    __syncthreads();
    if (t < 32) {
        float a = 0.f;
        for (int j = t; j < 100; j += 32) a = fmaf(s3[j], W4[j], a);
#pragma unroll
        for (int o = 16; o > 0; o >>= 1) a += __shfl_xor_sync(0xffffffffu, a, o);
        if (t == 0) out[b] = a + b4[0];
    }
}

// ---------------- launch ----------------
extern "C" void kernel_launch(void* const* d_in, const int* in_sizes, int n_in,
                              void* d_out, int out_size) {
    const float* atom1  = (const float*)d_in[0];
    const float* atom2  = (const float*)d_in[1];
    const float* coords1 = (const float*)d_in[2];
    const float* coords2 = (const float*)d_in[3];
    const float* ef1    = (const float*)d_in[4];
    const float* ef2    = (const float*)d_in[5];
    const float* int1   = (const float*)d_in[6];
    const float* int2   = (const float*)d_in[7];
    const int*   src1   = (const int*)d_in[8];
    const int*   dst1   = (const int*)d_in[9];
    const int*   src2   = (const int*)d_in[10];
    const int*   dst2   = (const int*)d_in[11];
    const float* W_atom = (const float*)d_in[12];
    const float* W_edge = (const float*)d_in[13];
    const float* W_rbf  = (const float*)d_in[14];
    const float* b_rbf  = (const float*)d_in[15];
    const float* ln_g   = (const float*)d_in[16];
    const float* ln_b   = (const float*)d_in[17];
    const float* W_down = (const float*)d_in[18];
    const float* dtab   = (const float*)d_in[19];
    const float* W_f1   = (const float*)d_in[20];
    const float* b_f1   = (const float*)d_in[21];
    const float* W_f2   = (const float*)d_in[22];
    const float* b_f2   = (const float*)d_in[23];
    const float* W_f3   = (const float*)d_in[24];
    const float* b_f3   = (const float*)d_in[25];
    const float* W_f4   = (const float*)d_in[26];
    const float* b_f4   = (const float*)d_in[27];
    float* out = (float*)d_out;

    const int SMEM_ATOM = (DA * DH + 8 * 2 * DA) * 4;
    const int SMEM_ATTN = (ATM * QSTR + ATK * QSTR + ATM * SSTR + 3 * ATM) * 4;

    cudaFuncSetAttribute(k_atom, cudaFuncAttributeMaxDynamicSharedMemorySize, SMEM_ATOM);
    cudaFuncSetAttribute(k_attn, cudaFuncAttributeMaxDynamicSharedMemorySize, SMEM_ATTN);

    // 0: atom GEMM + LN (also counts edge degrees)
    dim3 gatom(1024, 2);
    k_atom<<<gatom, 256, SMEM_ATOM>>>(atom1, atom2, dst1, dst2, W_atom, ln_g, ln_b);
    // 1: CSR scan
    k_scan<<<2, 1024>>>();
    // 2: CSR fill (+ counter re-zero)
    dim3 gedge(EE / 256, 2);
    k_fill<<<gedge, 256>>>(dst1, dst2);
    // 3: edge-message gather (profiled slot)
    dim3 ggath(1024, 2);
    k_gather<<<ggath, 128>>>(ef1, ef2, coords1, coords2, src1, src2,
                             W_edge, W_rbf, b_rbf, ln_g, ln_b);
    // 4: fused flash cross-attention + down projection + degree + tile means
    dim3 agrid(NNODES / ATM, BB, 2);
    k_attn<<<agrid, 256, SMEM_ATTN>>>(W_down, dtab);
    // 5: fused readout
    k_readout<<<BB, 256>>>(int1, int2, W_f1, b_f1, W_f2, b_f2,
                           W_f3, b_f3, W_f4, b_f4, out);
}